// round 4
// baseline (speedup 1.0000x reference)
#include <cuda_runtime.h>
#include <math.h>

// Problem constants
#define T_STEPS 128
#define BATCH   32
#define IN_DIM  128
#define OUT_DIM 128
#define N_SLOT  256
#define M_DIM   64
#define R_HEADS 4
#define H_DIM   256
#define ZC      1024   // 4*H

// ---------------- device scratch (no runtime allocation allowed) ----------------
__device__ float g_XW[T_STEPS * BATCH * ZC];     // precomputed x @ W_x + b  (16 MB)
__device__ float g_Wr[M_DIM * ZC];               // folded read-part of W_lstm
__device__ float g_Wro[M_DIM * OUT_DIM];         // folded W_ro
__device__ float g_lossPartial[BATCH];

// ---------------- shared-memory layout for the main kernel ----------------
#define OFF_MEM   0
#define OFF_Z     (OFF_MEM + N_SLOT * M_DIM)     // 16384
#define OFF_H     (OFF_Z + ZC)
#define OFF_C     (OFF_H + H_DIM)
#define OFF_READ  (OFF_C + H_DIM)
#define OFF_K     (OFF_READ + M_DIM)
#define OFF_TEACH (OFF_K + M_DIM)
#define OFF_PRE   (OFF_TEACH + M_DIM)
#define OFF_A     (OFF_PRE + OUT_DIM)
#define OFF_W     (OFF_A + N_SLOT)
#define OFF_PART  (OFF_W + N_SLOT)
#define OFF_HWP   (OFF_PART + 16 * M_DIM)
#define OFF_RED   (OFF_HWP + 260)                 // 257 padded to 260
#define OFF_SCAL  (OFF_RED + 32)
#define SM_FLOATS (OFF_SCAL + 8)
// scal: [0]=||k||, [1]=beta, [2]=softmax max, [3]=softmax sum, [4]=loss accum

// =================================================================
// Kernel 0: fold read-broadcast weights, done once per launch.
// Wr_eff[m][j] = sum_r W_lstm[(IN + 4m + r)][j]
// Wro_eff[m][j] = sum_r W_ro[(4m + r)][j]
// =================================================================
__global__ void fold_kernel(const float* __restrict__ W_lstm,
                            const float* __restrict__ W_ro) {
    int idx = blockIdx.x * blockDim.x + threadIdx.x;
    if (idx < M_DIM * ZC) {
        int m = idx / ZC, j = idx - m * ZC;
        float s = 0.f;
        #pragma unroll
        for (int r = 0; r < R_HEADS; r++)
            s += W_lstm[(IN_DIM + 4 * m + r) * ZC + j];
        g_Wr[idx] = s;
    } else if (idx < M_DIM * ZC + M_DIM * OUT_DIM) {
        int i2 = idx - M_DIM * ZC;
        int m = i2 / OUT_DIM, j = i2 - m * OUT_DIM;
        float s = 0.f;
        #pragma unroll
        for (int r = 0; r < R_HEADS; r++)
            s += W_ro[(4 * m + r) * OUT_DIM + j];
        g_Wro[i2] = s;
    }
}

// =================================================================
// Kernel 1: XW[t,b,:] = xs[t,b,:] @ W_lstm[0:IN,:] + b_lstm
// GEMM M=4096, K=128, N=1024. 64x64 tiles, 256 threads, 4x4 per thread.
// =================================================================
__global__ void xw_kernel(const float* __restrict__ xs,
                          const float* __restrict__ W,
                          const float* __restrict__ bias) {
    __shared__ float As[64][65];
    __shared__ float Bs[64][68];   // stride 68 floats keeps float4 alignment

    int tid = threadIdx.x;
    int tx = tid & 15, ty = tid >> 4;
    int r0 = blockIdx.y * 64;      // row tile (T*B rows)
    int c0 = blockIdx.x * 64;      // col tile (1024 cols)

    float acc[4][4] = {};

    for (int kc = 0; kc < IN_DIM; kc += 64) {
        // load A tile: 64 rows x 64 k  (xs is [4096,128] row-major)
        for (int e = tid; e < 1024; e += 256) {
            int i = e >> 4;
            int cc4 = (e & 15) << 2;
            float4 v = *(const float4*)(xs + (size_t)(r0 + i) * IN_DIM + kc + cc4);
            As[i][cc4 + 0] = v.x; As[i][cc4 + 1] = v.y;
            As[i][cc4 + 2] = v.z; As[i][cc4 + 3] = v.w;
        }
        // load B tile: 64 k x 64 cols (W is [640,1024] row-major)
        for (int e = tid; e < 1024; e += 256) {
            int kk = e >> 4;
            int cc4 = (e & 15) << 2;
            float4 v = *(const float4*)(W + (size_t)(kc + kk) * ZC + c0 + cc4);
            *(float4*)&Bs[kk][cc4] = v;
        }
        __syncthreads();
        #pragma unroll
        for (int kk = 0; kk < 64; kk++) {
            float4 bv = *(float4*)&Bs[kk][tx << 2];
            float a0 = As[ty * 4 + 0][kk];
            float a1 = As[ty * 4 + 1][kk];
            float a2 = As[ty * 4 + 2][kk];
            float a3 = As[ty * 4 + 3][kk];
            acc[0][0] += a0 * bv.x; acc[0][1] += a0 * bv.y; acc[0][2] += a0 * bv.z; acc[0][3] += a0 * bv.w;
            acc[1][0] += a1 * bv.x; acc[1][1] += a1 * bv.y; acc[1][2] += a1 * bv.z; acc[1][3] += a1 * bv.w;
            acc[2][0] += a2 * bv.x; acc[2][1] += a2 * bv.y; acc[2][2] += a2 * bv.z; acc[2][3] += a2 * bv.w;
            acc[3][0] += a3 * bv.x; acc[3][1] += a3 * bv.y; acc[3][2] += a3 * bv.z; acc[3][3] += a3 * bv.w;
        }
        __syncthreads();
    }

    float4 bb = *(const float4*)(bias + c0 + (tx << 2));
    #pragma unroll
    for (int u = 0; u < 4; u++) {
        int row = r0 + ty * 4 + u;
        float4 o;
        o.x = acc[u][0] + bb.x; o.y = acc[u][1] + bb.y;
        o.z = acc[u][2] + bb.z; o.w = acc[u][3] + bb.w;
        *(float4*)(g_XW + (size_t)row * ZC + c0 + (tx << 2)) = o;
    }
}

// =================================================================
// Kernel 2: the sequential recurrence. One block per batch.
// =================================================================
__global__ void __launch_bounds__(1024, 1)
dnc_main_kernel(const float* __restrict__ mem0,
                const float* __restrict__ W_lstm,
                const float* __restrict__ W_pre,
                const float* __restrict__ b_pre,
                const float* __restrict__ W_key,
                const float* __restrict__ W_beta,
                const float* __restrict__ W_teach,
                float* __restrict__ d_out,
                int out_size) {
    extern __shared__ float sm[];
    float* memS   = sm + OFF_MEM;
    float* zS     = sm + OFF_Z;
    float* hS     = sm + OFF_H;
    float* cS     = sm + OFF_C;
    float* readS  = sm + OFF_READ;
    float* kS     = sm + OFF_K;
    float* teachS = sm + OFF_TEACH;
    float* preS   = sm + OFF_PRE;
    float* aS     = sm + OFF_A;
    float* wS     = sm + OFF_W;
    float* partS  = sm + OFF_PART;
    float* hwpS   = sm + OFF_HWP;
    float* redS   = sm + OFF_RED;
    float* scal   = sm + OFF_SCAL;

    const int b = blockIdx.x;
    const int tid = threadIdx.x;
    const float* Wh = W_lstm + (size_t)(IN_DIM + M_DIM * R_HEADS) * ZC; // h-rows

    // ---- init: memory into SMEM, zero state ----
    {
        const float4* m0 = (const float4*)(mem0 + (size_t)b * N_SLOT * M_DIM);
        float4* ms = (float4*)memS;
        for (int i = tid; i < N_SLOT * M_DIM / 4; i += 1024) ms[i] = m0[i];
    }
    if (tid < H_DIM) { hS[tid] = 0.f; cS[tid] = 0.f; }
    if (tid < M_DIM) readS[tid] = 0.f;
    if (tid == 0) scal[4] = 0.f;
    __syncthreads();

    for (int t = 0; t < T_STEPS; t++) {
        // ---------- phase 1: z = XW[t,b] + read @ Wr_eff + h @ Wh ----------
        {
            float acc = g_XW[((size_t)t * BATCH + b) * ZC + tid];
            #pragma unroll 8
            for (int m = 0; m < M_DIM; m++)
                acc += readS[m] * g_Wr[m * ZC + tid];
            #pragma unroll 8
            for (int hh = 0; hh < H_DIM; hh++)
                acc += hS[hh] * Wh[(size_t)hh * ZC + tid];
            zS[tid] = acc;
        }
        __syncthreads();

        // ---------- phase 2: LSTM gates ----------
        if (tid < H_DIM) {
            float iv = zS[tid], fv = zS[tid + 256], gv = zS[tid + 512], ov = zS[tid + 768];
            float si = 1.f / (1.f + expf(-iv));
            float sf = 1.f / (1.f + expf(-fv));
            float so = 1.f / (1.f + expf(-ov));
            float cn = sf * cS[tid] + si * tanhf(gv);
            cS[tid] = cn;
            hS[tid] = so * tanhf(cn);
        }
        __syncthreads();

        // ---------- phase 3: h @ [W_pre | W_key | W_beta | W_teach], 2-way K split ----------
        float part_acc = 0.f;
        int col = tid >> 1;
        int half = tid & 1;
        if (tid < 514) {
            const float* Wc; int ld, c2;
            if (col < 128)      { Wc = W_pre;   ld = 128; c2 = col; }
            else if (col < 192) { Wc = W_key;   ld = 64;  c2 = col - 128; }
            else if (col < 256) { Wc = W_teach; ld = 64;  c2 = col - 192; }
            else                { Wc = W_beta;  ld = 1;   c2 = 0; }
            int h0 = half * 128;
            #pragma unroll 8
            for (int hh = 0; hh < 128; hh++)
                part_acc += hS[h0 + hh] * Wc[(size_t)(h0 + hh) * ld + c2];
            if (half) hwpS[col] = part_acc;
        }
        __syncthreads();
        if (tid < 514 && half == 0) {
            float full = part_acc + hwpS[col];
            if (col < 128)      preS[col] = full + b_pre[col];
            else if (col < 192) kS[col - 128] = full;
            else if (col < 256) teachS[col - 192] = full;
            else { // softplus, numerically stable
                float x = full;
                scal[1] = fmaxf(x, 0.f) + log1pf(expf(-fabsf(x)));
            }
        }
        __syncthreads();

        // ---------- phase 4: ||k||, and loss term sum_m (k - teacher)^2 ----------
        if (tid < 32) {
            float k1 = kS[tid], k2 = kS[tid + 32];
            float t1 = teachS[tid], t2 = teachS[tid + 32];
            float nk = k1 * k1 + k2 * k2;
            float d1 = k1 - t1, d2 = k2 - t2;
            float ls = d1 * d1 + d2 * d2;
            #pragma unroll
            for (int o = 16; o > 0; o >>= 1) {
                nk += __shfl_xor_sync(0xffffffffu, nk, o);
                ls += __shfl_xor_sync(0xffffffffu, ls, o);
            }
            if (tid == 0) { scal[0] = sqrtf(nk); scal[4] += ls; }
        }
        __syncthreads();

        // ---------- phase 5: cosine sim per slot (4 threads/slot), slot norms recomputed ----------
        {
            int n = tid >> 2, tt = tid & 3;
            const float4* mr = (const float4*)(memS + n * M_DIM + tt * 16);
            const float4* kk = (const float4*)(kS + tt * 16);
            float s1 = 0.f, s2 = 0.f;
            #pragma unroll
            for (int i = 0; i < 4; i++) {
                float4 mv = mr[i]; float4 kv = kk[i];
                s1 += mv.x * kv.x + mv.y * kv.y + mv.z * kv.z + mv.w * kv.w;
                s2 += mv.x * mv.x + mv.y * mv.y + mv.z * mv.z + mv.w * mv.w;
            }
            s1 += __shfl_xor_sync(0xffffffffu, s1, 1);
            s2 += __shfl_xor_sync(0xffffffffu, s2, 1);
            s1 += __shfl_xor_sync(0xffffffffu, s1, 2);
            s2 += __shfl_xor_sync(0xffffffffu, s2, 2);
            if (tt == 0) {
                float den = fmaxf(sqrtf(s2) * scal[0], 1e-8f);
                aS[n] = scal[1] * (s1 / den);
            }
        }
        __syncthreads();

        // ---------- phase 6: softmax over 256 slots ----------
        {
            float av = (tid < N_SLOT) ? aS[tid] : -1e30f;
            float mv = av;
            #pragma unroll
            for (int o = 16; o > 0; o >>= 1)
                mv = fmaxf(mv, __shfl_xor_sync(0xffffffffu, mv, o));
            if ((tid & 31) == 0) redS[tid >> 5] = mv;
            __syncthreads();
            if (tid < 32) {
                float v = redS[tid];
                #pragma unroll
                for (int o = 16; o > 0; o >>= 1)
                    v = fmaxf(v, __shfl_xor_sync(0xffffffffu, v, o));
                if (tid == 0) scal[2] = v;
            }
            __syncthreads();
            float ev = (tid < N_SLOT) ? expf(aS[tid] - scal[2]) : 0.f;
            if (tid < N_SLOT) wS[tid] = ev;
            float sv = ev;
            #pragma unroll
            for (int o = 16; o > 0; o >>= 1)
                sv += __shfl_xor_sync(0xffffffffu, sv, o);
            if ((tid & 31) == 0) redS[tid >> 5] = sv;
            __syncthreads();
            if (tid < 32) {
                float v = redS[tid];
                #pragma unroll
                for (int o = 16; o > 0; o >>= 1)
                    v += __shfl_xor_sync(0xffffffffu, v, o);
                if (tid == 0) scal[3] = v;
            }
            __syncthreads();
            if (tid < N_SLOT) wS[tid] *= (1.f / scal[3]);
        }
        __syncthreads();

        // ---------- phase 7: mem += w (x) k; read = w @ mem_new ----------
        {
            int m = tid & 63, g = tid >> 6;      // g in [0,16)
            float kv = kS[m];
            float rp = 0.f;
            #pragma unroll
            for (int s = 0; s < 16; s++) {
                int n = g * 16 + s;
                float wv = wS[n];
                float v = memS[n * M_DIM + m] + wv * kv;
                memS[n * M_DIM + m] = v;
                rp += wv * v;
            }
            partS[g * M_DIM + m] = rp;
        }
        __syncthreads();
        if (tid < M_DIM) {
            float r = 0.f;
            #pragma unroll
            for (int g2 = 0; g2 < 16; g2++) r += partS[g2 * M_DIM + tid];
            readS[tid] = r;
        }
        __syncthreads();

        // ---------- phase 8: out = pre_out + read @ Wro_eff ----------
        if (tid < OUT_DIM) {
            float o = preS[tid];
            #pragma unroll 8
            for (int m2 = 0; m2 < M_DIM; m2++)
                o += readS[m2] * g_Wro[m2 * OUT_DIM + tid];
            d_out[((size_t)t * BATCH + b) * OUT_DIM + tid] = o;
        }
        __syncthreads();
    }

    if (tid == 0) g_lossPartial[b] = scal[4];
}

// =================================================================
// Kernel 3: finalize loss = sum_b L_b / (B*M)
// =================================================================
__global__ void finalize_kernel(float* d_out, int out_size) {
    if (threadIdx.x == 0) {
        float s = 0.f;
        for (int b = 0; b < BATCH; b++) s += g_lossPartial[b];
        d_out[out_size - 1] = s / (float)(BATCH * M_DIM);
    }
}

// =================================================================
extern "C" void kernel_launch(void* const* d_in, const int* in_sizes, int n_in,
                              void* d_out, int out_size) {
    const float* xs      = (const float*)d_in[0];
    const float* mem0    = (const float*)d_in[1];
    const float* W_lstm  = (const float*)d_in[2];
    const float* b_lstm  = (const float*)d_in[3];
    const float* W_pre   = (const float*)d_in[4];
    const float* b_pre   = (const float*)d_in[5];
    const float* W_key   = (const float*)d_in[6];
    const float* W_beta  = (const float*)d_in[7];
    const float* W_teach = (const float*)d_in[8];
    const float* W_ro    = (const float*)d_in[9];
    float* out = (float*)d_out;

    const int smem_bytes = SM_FLOATS * (int)sizeof(float);
    cudaFuncSetAttribute(dnc_main_kernel,
                         cudaFuncAttributeMaxDynamicSharedMemorySize, smem_bytes);

    int fold_total = M_DIM * ZC + M_DIM * OUT_DIM;
    fold_kernel<<<(fold_total + 255) / 256, 256>>>(W_lstm, W_ro);
    xw_kernel<<<dim3(ZC / 64, T_STEPS * BATCH / 64), 256>>>(xs, W_lstm, b_lstm);
    dnc_main_kernel<<<BATCH, 1024, smem_bytes>>>(mem0, W_lstm, W_pre, b_pre,
                                                 W_key, W_beta, W_teach,
                                                 out, out_size);
    finalize_kernel<<<1, 32>>>(out, out_size);
}

// round 6
// speedup vs baseline: 1.0023x; 1.0023x over previous
#include <cuda_runtime.h>
#include <math.h>

// Problem constants
#define T_STEPS 128
#define BATCH   32
#define IN_DIM  128
#define OUT_DIM 128
#define N_SLOT  256
#define M_DIM   64
#define R_HEADS 4
#define H_DIM   256
#define ZC      1024   // 4*H

// ---------------- device scratch (no runtime allocation allowed) ----------------
__device__ float g_XW[T_STEPS * BATCH * ZC];     // precomputed x @ W_x + b  (16 MB)
__device__ float g_Wr[M_DIM * ZC];               // folded read-part of W_lstm
__device__ float g_Wro[M_DIM * OUT_DIM];         // folded W_ro
__device__ float g_lossPartial[BATCH];

// ---------------- shared-memory layout for the main kernel ----------------
#define OFF_MEM   0
#define OFF_Z     (OFF_MEM + N_SLOT * M_DIM)     // 16384
#define OFF_H     (OFF_Z + ZC)
#define OFF_C     (OFF_H + H_DIM)
#define OFF_READ  (OFF_C + H_DIM)
#define OFF_K     (OFF_READ + M_DIM)
#define OFF_TEACH (OFF_K + M_DIM)
#define OFF_PRE   (OFF_TEACH + M_DIM)
#define OFF_A     (OFF_PRE + OUT_DIM)
#define OFF_W     (OFF_A + N_SLOT)
#define OFF_PART  (OFF_W + N_SLOT)
#define OFF_HWP   (OFF_PART + 16 * M_DIM)
#define OFF_RED   (OFF_HWP + 260)                 // 257 padded to 260
#define OFF_SCAL  (OFF_RED + 32)
#define SM_FLOATS (OFF_SCAL + 8)
// scal: [0]=||k||, [1]=beta, [2]=softmax max, [3]=softmax sum, [4]=loss accum

// =================================================================
// Kernel 0: fold read-broadcast weights, done once per launch.
// Wr_eff[m][j] = sum_r W_lstm[(IN + 4m + r)][j]
// Wro_eff[m][j] = sum_r W_ro[(4m + r)][j]
// =================================================================
__global__ void fold_kernel(const float* __restrict__ W_lstm,
                            const float* __restrict__ W_ro) {
    int idx = blockIdx.x * blockDim.x + threadIdx.x;
    if (idx < M_DIM * ZC) {
        int m = idx / ZC, j = idx - m * ZC;
        float s = 0.f;
        #pragma unroll
        for (int r = 0; r < R_HEADS; r++)
            s += W_lstm[(IN_DIM + 4 * m + r) * ZC + j];
        g_Wr[idx] = s;
    } else if (idx < M_DIM * ZC + M_DIM * OUT_DIM) {
        int i2 = idx - M_DIM * ZC;
        int m = i2 / OUT_DIM, j = i2 - m * OUT_DIM;
        float s = 0.f;
        #pragma unroll
        for (int r = 0; r < R_HEADS; r++)
            s += W_ro[(4 * m + r) * OUT_DIM + j];
        g_Wro[i2] = s;
    }
}

// =================================================================
// Kernel 1: XW[t,b,:] = xs[t,b,:] @ W_lstm[0:IN,:] + b_lstm
// GEMM M=4096, K=128, N=1024. 64x64 tiles, 256 threads, 4x4 per thread.
// =================================================================
__global__ void xw_kernel(const float* __restrict__ xs,
                          const float* __restrict__ W,
                          const float* __restrict__ bias) {
    __shared__ float As[64][65];
    __shared__ float Bs[64][68];   // stride 68 floats keeps float4 alignment

    int tid = threadIdx.x;
    int tx = tid & 15, ty = tid >> 4;
    int r0 = blockIdx.y * 64;      // row tile (T*B rows)
    int c0 = blockIdx.x * 64;      // col tile (1024 cols)

    float acc[4][4] = {};

    for (int kc = 0; kc < IN_DIM; kc += 64) {
        // load A tile: 64 rows x 64 k  (xs is [4096,128] row-major)
        for (int e = tid; e < 1024; e += 256) {
            int i = e >> 4;
            int cc4 = (e & 15) << 2;
            float4 v = *(const float4*)(xs + (size_t)(r0 + i) * IN_DIM + kc + cc4);
            As[i][cc4 + 0] = v.x; As[i][cc4 + 1] = v.y;
            As[i][cc4 + 2] = v.z; As[i][cc4 + 3] = v.w;
        }
        // load B tile: 64 k x 64 cols (W is [640,1024] row-major)
        for (int e = tid; e < 1024; e += 256) {
            int kk = e >> 4;
            int cc4 = (e & 15) << 2;
            float4 v = *(const float4*)(W + (size_t)(kc + kk) * ZC + c0 + cc4);
            *(float4*)&Bs[kk][cc4] = v;
        }
        __syncthreads();
        #pragma unroll
        for (int kk = 0; kk < 64; kk++) {
            float4 bv = *(float4*)&Bs[kk][tx << 2];
            float a0 = As[ty * 4 + 0][kk];
            float a1 = As[ty * 4 + 1][kk];
            float a2 = As[ty * 4 + 2][kk];
            float a3 = As[ty * 4 + 3][kk];
            acc[0][0] += a0 * bv.x; acc[0][1] += a0 * bv.y; acc[0][2] += a0 * bv.z; acc[0][3] += a0 * bv.w;
            acc[1][0] += a1 * bv.x; acc[1][1] += a1 * bv.y; acc[1][2] += a1 * bv.z; acc[1][3] += a1 * bv.w;
            acc[2][0] += a2 * bv.x; acc[2][1] += a2 * bv.y; acc[2][2] += a2 * bv.z; acc[2][3] += a2 * bv.w;
            acc[3][0] += a3 * bv.x; acc[3][1] += a3 * bv.y; acc[3][2] += a3 * bv.z; acc[3][3] += a3 * bv.w;
        }
        __syncthreads();
    }

    float4 bb = *(const float4*)(bias + c0 + (tx << 2));
    #pragma unroll
    for (int u = 0; u < 4; u++) {
        int row = r0 + ty * 4 + u;
        float4 o;
        o.x = acc[u][0] + bb.x; o.y = acc[u][1] + bb.y;
        o.z = acc[u][2] + bb.z; o.w = acc[u][3] + bb.w;
        *(float4*)(g_XW + (size_t)row * ZC + c0 + (tx << 2)) = o;
    }
}

// =================================================================
// Kernel 2: the sequential recurrence. One block per batch.
// =================================================================
__global__ void __launch_bounds__(1024, 1)
dnc_main_kernel(const float* __restrict__ mem0,
                const float* __restrict__ W_lstm,
                const float* __restrict__ W_pre,
                const float* __restrict__ b_pre,
                const float* __restrict__ W_key,
                const float* __restrict__ W_beta,
                const float* __restrict__ W_teach,
                float* __restrict__ d_out,
                int out_size) {
    extern __shared__ float sm[];
    float* memS   = sm + OFF_MEM;
    float* zS     = sm + OFF_Z;
    float* hS     = sm + OFF_H;
    float* cS     = sm + OFF_C;
    float* readS  = sm + OFF_READ;
    float* kS     = sm + OFF_K;
    float* teachS = sm + OFF_TEACH;
    float* preS   = sm + OFF_PRE;
    float* aS     = sm + OFF_A;
    float* wS     = sm + OFF_W;
    float* partS  = sm + OFF_PART;
    float* hwpS   = sm + OFF_HWP;
    float* redS   = sm + OFF_RED;
    float* scal   = sm + OFF_SCAL;

    const int b = blockIdx.x;
    const int tid = threadIdx.x;
    const float* Wh = W_lstm + (size_t)(IN_DIM + M_DIM * R_HEADS) * ZC; // h-rows

    // ---- init: memory into SMEM, zero state ----
    {
        const float4* m0 = (const float4*)(mem0 + (size_t)b * N_SLOT * M_DIM);
        float4* ms = (float4*)memS;
        for (int i = tid; i < N_SLOT * M_DIM / 4; i += 1024) ms[i] = m0[i];
    }
    if (tid < H_DIM) { hS[tid] = 0.f; cS[tid] = 0.f; }
    if (tid < M_DIM) readS[tid] = 0.f;
    if (tid == 0) scal[4] = 0.f;
    __syncthreads();

    for (int t = 0; t < T_STEPS; t++) {
        // ---------- phase 1: z = XW[t,b] + read @ Wr_eff + h @ Wh ----------
        {
            float acc = g_XW[((size_t)t * BATCH + b) * ZC + tid];
            #pragma unroll 8
            for (int m = 0; m < M_DIM; m++)
                acc += readS[m] * g_Wr[m * ZC + tid];
            #pragma unroll 8
            for (int hh = 0; hh < H_DIM; hh++)
                acc += hS[hh] * Wh[(size_t)hh * ZC + tid];
            zS[tid] = acc;
        }
        __syncthreads();

        // ---------- phase 2: LSTM gates ----------
        if (tid < H_DIM) {
            float iv = zS[tid], fv = zS[tid + 256], gv = zS[tid + 512], ov = zS[tid + 768];
            float si = 1.f / (1.f + expf(-iv));
            float sf = 1.f / (1.f + expf(-fv));
            float so = 1.f / (1.f + expf(-ov));
            float cn = sf * cS[tid] + si * tanhf(gv);
            cS[tid] = cn;
            hS[tid] = so * tanhf(cn);
        }
        __syncthreads();

        // ---------- phase 3: h @ [W_pre | W_key | W_beta | W_teach], 2-way K split ----------
        float part_acc = 0.f;
        int col = tid >> 1;
        int half = tid & 1;
        if (tid < 514) {
            const float* Wc; int ld, c2;
            if (col < 128)      { Wc = W_pre;   ld = 128; c2 = col; }
            else if (col < 192) { Wc = W_key;   ld = 64;  c2 = col - 128; }
            else if (col < 256) { Wc = W_teach; ld = 64;  c2 = col - 192; }
            else                { Wc = W_beta;  ld = 1;   c2 = 0; }
            int h0 = half * 128;
            #pragma unroll 8
            for (int hh = 0; hh < 128; hh++)
                part_acc += hS[h0 + hh] * Wc[(size_t)(h0 + hh) * ld + c2];
            if (half) hwpS[col] = part_acc;
        }
        __syncthreads();
        if (tid < 514 && half == 0) {
            float full = part_acc + hwpS[col];
            if (col < 128)      preS[col] = full + b_pre[col];
            else if (col < 192) kS[col - 128] = full;
            else if (col < 256) teachS[col - 192] = full;
            else { // softplus, numerically stable
                float x = full;
                scal[1] = fmaxf(x, 0.f) + log1pf(expf(-fabsf(x)));
            }
        }
        __syncthreads();

        // ---------- phase 4: ||k||, and loss term sum_m (k - teacher)^2 ----------
        if (tid < 32) {
            float k1 = kS[tid], k2 = kS[tid + 32];
            float t1 = teachS[tid], t2 = teachS[tid + 32];
            float nk = k1 * k1 + k2 * k2;
            float d1 = k1 - t1, d2 = k2 - t2;
            float ls = d1 * d1 + d2 * d2;
            #pragma unroll
            for (int o = 16; o > 0; o >>= 1) {
                nk += __shfl_xor_sync(0xffffffffu, nk, o);
                ls += __shfl_xor_sync(0xffffffffu, ls, o);
            }
            if (tid == 0) { scal[0] = sqrtf(nk); scal[4] += ls; }
        }
        __syncthreads();

        // ---------- phase 5: cosine sim per slot (4 threads/slot), slot norms recomputed ----------
        {
            int n = tid >> 2, tt = tid & 3;
            const float4* mr = (const float4*)(memS + n * M_DIM + tt * 16);
            const float4* kk = (const float4*)(kS + tt * 16);
            float s1 = 0.f, s2 = 0.f;
            #pragma unroll
            for (int i = 0; i < 4; i++) {
                float4 mv = mr[i]; float4 kv = kk[i];
                s1 += mv.x * kv.x + mv.y * kv.y + mv.z * kv.z + mv.w * kv.w;
                s2 += mv.x * mv.x + mv.y * mv.y + mv.z * mv.z + mv.w * mv.w;
            }
            s1 += __shfl_xor_sync(0xffffffffu, s1, 1);
            s2 += __shfl_xor_sync(0xffffffffu, s2, 1);
            s1 += __shfl_xor_sync(0xffffffffu, s1, 2);
            s2 += __shfl_xor_sync(0xffffffffu, s2, 2);
            if (tt == 0) {
                float den = fmaxf(sqrtf(s2) * scal[0], 1e-8f);
                aS[n] = scal[1] * (s1 / den);
            }
        }
        __syncthreads();

        // ---------- phase 6: softmax over 256 slots ----------
        {
            float av = (tid < N_SLOT) ? aS[tid] : -1e30f;
            float mv = av;
            #pragma unroll
            for (int o = 16; o > 0; o >>= 1)
                mv = fmaxf(mv, __shfl_xor_sync(0xffffffffu, mv, o));
            if ((tid & 31) == 0) redS[tid >> 5] = mv;
            __syncthreads();
            if (tid < 32) {
                float v = redS[tid];
                #pragma unroll
                for (int o = 16; o > 0; o >>= 1)
                    v = fmaxf(v, __shfl_xor_sync(0xffffffffu, v, o));
                if (tid == 0) scal[2] = v;
            }
            __syncthreads();
            float ev = (tid < N_SLOT) ? expf(aS[tid] - scal[2]) : 0.f;
            if (tid < N_SLOT) wS[tid] = ev;
            float sv = ev;
            #pragma unroll
            for (int o = 16; o > 0; o >>= 1)
                sv += __shfl_xor_sync(0xffffffffu, sv, o);
            if ((tid & 31) == 0) redS[tid >> 5] = sv;
            __syncthreads();
            if (tid < 32) {
                float v = redS[tid];
                #pragma unroll
                for (int o = 16; o > 0; o >>= 1)
                    v += __shfl_xor_sync(0xffffffffu, v, o);
                if (tid == 0) scal[3] = v;
            }
            __syncthreads();
            if (tid < N_SLOT) wS[tid] *= (1.f / scal[3]);
        }
        __syncthreads();

        // ---------- phase 7: mem += w (x) k; read = w @ mem_new ----------
        {
            int m = tid & 63, g = tid >> 6;      // g in [0,16)
            float kv = kS[m];
            float rp = 0.f;
            #pragma unroll
            for (int s = 0; s < 16; s++) {
                int n = g * 16 + s;
                float wv = wS[n];
                float v = memS[n * M_DIM + m] + wv * kv;
                memS[n * M_DIM + m] = v;
                rp += wv * v;
            }
            partS[g * M_DIM + m] = rp;
        }
        __syncthreads();
        if (tid < M_DIM) {
            float r = 0.f;
            #pragma unroll
            for (int g2 = 0; g2 < 16; g2++) r += partS[g2 * M_DIM + tid];
            readS[tid] = r;
        }
        __syncthreads();

        // ---------- phase 8: out = pre_out + read @ Wro_eff ----------
        if (tid < OUT_DIM) {
            float o = preS[tid];
            #pragma unroll 8
            for (int m2 = 0; m2 < M_DIM; m2++)
                o += readS[m2] * g_Wro[m2 * OUT_DIM + tid];
            d_out[((size_t)t * BATCH + b) * OUT_DIM + tid] = o;
        }
        __syncthreads();
    }

    if (tid == 0) g_lossPartial[b] = scal[4];
}

// =================================================================
// Kernel 3: finalize loss = sum_b L_b / (B*M)
// =================================================================
__global__ void finalize_kernel(float* d_out, int out_size) {
    if (threadIdx.x == 0) {
        float s = 0.f;
        for (int b = 0; b < BATCH; b++) s += g_lossPartial[b];
        d_out[out_size - 1] = s / (float)(BATCH * M_DIM);
    }
}

// =================================================================
extern "C" void kernel_launch(void* const* d_in, const int* in_sizes, int n_in,
                              void* d_out, int out_size) {
    const float* xs      = (const float*)d_in[0];
    const float* mem0    = (const float*)d_in[1];
    const float* W_lstm  = (const float*)d_in[2];
    const float* b_lstm  = (const float*)d_in[3];
    const float* W_pre   = (const float*)d_in[4];
    const float* b_pre   = (const float*)d_in[5];
    const float* W_key   = (const float*)d_in[6];
    const float* W_beta  = (const float*)d_in[7];
    const float* W_teach = (const float*)d_in[8];
    const float* W_ro    = (const float*)d_in[9];
    float* out = (float*)d_out;

    const int smem_bytes = SM_FLOATS * (int)sizeof(float);
    cudaFuncSetAttribute(dnc_main_kernel,
                         cudaFuncAttributeMaxDynamicSharedMemorySize, smem_bytes);

    int fold_total = M_DIM * ZC + M_DIM * OUT_DIM;
    fold_kernel<<<(fold_total + 255) / 256, 256>>>(W_lstm, W_ro);
    xw_kernel<<<dim3(ZC / 64, T_STEPS * BATCH / 64), 256>>>(xs, W_lstm, b_lstm);
    dnc_main_kernel<<<BATCH, 1024, smem_bytes>>>(mem0, W_lstm, W_pre, b_pre,
                                                 W_key, W_beta, W_teach,
                                                 out, out_size);
    finalize_kernel<<<1, 32>>>(out, out_size);
}

// round 7
// speedup vs baseline: 1.2727x; 1.2698x over previous
#include <cuda_runtime.h>
#include <math.h>
#include <stdint.h>

// Problem constants
#define T_STEPS 128
#define BATCH   32
#define IN_DIM  128
#define OUT_DIM 128
#define N_SLOT  256
#define M_DIM   64
#define R_HEADS 4
#define H_DIM   256
#define ZC      1024   // 4*H
#define KROWS   320    // 64 folded read rows + 256 h rows
#define HALF    512    // z columns per CTA (cluster of 2)

// ---------------- device scratch ----------------
__device__ float g_XWp[T_STEPS * BATCH * ZC];      // x@Wx + b, permuted cols (16 MB)
__device__ float g_Wz[2 * KROWS * HALF];           // blocked z-weights per rank (1.31 MB)
__device__ float g_Wro[M_DIM * OUT_DIM];           // folded W_ro
__device__ float g_lossPartial[BATCH];

// ---------------- shared memory layout (floats) ----------------
#define OFF_MEM   0
#define OFF_PS    (OFF_MEM + N_SLOT * M_DIM)   // 16384 : GEMV partials 8x512 (reused ph7)
#define OFF_Z     (OFF_PS + 4096)              // 20480 : z slice [512]
#define OFF_HA    (OFF_Z + HALF)               // h buffer 0 [256]
#define OFF_HB    (OFF_HA + H_DIM)             // h buffer 1 [256]
#define OFF_S     (OFF_HB + H_DIM)             // s vector [320] = read|h_prev
#define OFF_C     (OFF_S + KROWS)              // c slice [128]
#define OFF_READ  (OFF_C + 128)                // [64]
#define OFF_K     (OFF_READ + M_DIM)           // [64]
#define OFF_TEACH (OFF_K + M_DIM)              // [64]
#define OFF_PRE   (OFF_TEACH + M_DIM)          // [128]
#define OFF_A     (OFF_PRE + OUT_DIM)          // [256]
#define OFF_W     (OFF_A + N_SLOT)             // [256]
#define OFF_HWP   (OFF_W + N_SLOT)             // [260]
#define OFF_RED   (OFF_HWP + 260)              // [32]
#define OFF_SCAL  (OFF_RED + 32)               // [8]
#define SM_FLOATS (OFF_SCAL + 8)
// scal: [0]=||k||, [1]=beta, [2]=smax max, [3]=smax sum, [4]=loss accum

#define CLUSTER_SYNC() do { \
    asm volatile("barrier.cluster.arrive.aligned;" ::: "memory"); \
    asm volatile("barrier.cluster.wait.aligned;" ::: "memory"); \
} while (0)

__device__ __forceinline__ uint32_t smem_u32(const void* p) {
    uint32_t a;
    asm("{ .reg .u64 t; cvta.to.shared.u64 t, %1; cvt.u32.u64 %0, t; }"
        : "=r"(a) : "l"(p));
    return a;
}
__device__ __forceinline__ void st_peer(uint32_t laddr, uint32_t peer, float v) {
    uint32_t raddr;
    asm volatile("mapa.shared::cluster.u32 %0, %1, %2;" : "=r"(raddr) : "r"(laddr), "r"(peer));
    asm volatile("st.shared::cluster.f32 [%0], %1;" :: "r"(raddr), "f"(v) : "memory");
}

// =================================================================
// Kernel 0: build g_Wz (folded read rows + h rows, gate-aligned permuted
// columns, blocked per cluster rank) and folded g_Wro.
// g_Wz[(r*320+k)*512 + lc], lc = g*128 + lj, orig col = g*256 + r*128 + lj.
// =================================================================
__global__ void fold_kernel(const float* __restrict__ W_lstm,
                            const float* __restrict__ W_ro) {
    int idx = blockIdx.x * blockDim.x + threadIdx.x;
    const int NZ = 2 * KROWS * HALF;
    if (idx < NZ) {
        int r  = idx / (KROWS * HALF);
        int k  = (idx / HALF) % KROWS;
        int lc = idx & (HALF - 1);
        int g  = lc >> 7, lj = lc & 127;
        int col = g * 256 + r * 128 + lj;
        float s;
        if (k < 64) {
            s = 0.f;
            #pragma unroll
            for (int rr = 0; rr < R_HEADS; rr++)
                s += W_lstm[(size_t)(IN_DIM + 4 * k + rr) * ZC + col];
        } else {
            s = W_lstm[(size_t)(IN_DIM + 256 + (k - 64)) * ZC + col];
        }
        g_Wz[idx] = s;
    } else if (idx < NZ + M_DIM * OUT_DIM) {
        int i2 = idx - NZ;
        int m = i2 / OUT_DIM, j = i2 - m * OUT_DIM;
        float s = 0.f;
        #pragma unroll
        for (int r = 0; r < R_HEADS; r++)
            s += W_ro[(size_t)(4 * m + r) * OUT_DIM + j];
        g_Wro[i2] = s;
    }
}

// =================================================================
// Kernel 1: XW = xs @ W_lstm[0:IN,:] + b_lstm, stored with permuted columns.
// =================================================================
__global__ void xw_kernel(const float* __restrict__ xs,
                          const float* __restrict__ W,
                          const float* __restrict__ bias) {
    __shared__ float As[64][65];
    __shared__ float Bs[64][68];

    int tid = threadIdx.x;
    int tx = tid & 15, ty = tid >> 4;
    int r0 = blockIdx.y * 64;
    int c0 = blockIdx.x * 64;

    float acc[4][4] = {};

    for (int kc = 0; kc < IN_DIM; kc += 64) {
        for (int e = tid; e < 1024; e += 256) {
            int i = e >> 4;
            int cc4 = (e & 15) << 2;
            float4 v = *(const float4*)(xs + (size_t)(r0 + i) * IN_DIM + kc + cc4);
            As[i][cc4 + 0] = v.x; As[i][cc4 + 1] = v.y;
            As[i][cc4 + 2] = v.z; As[i][cc4 + 3] = v.w;
        }
        for (int e = tid; e < 1024; e += 256) {
            int kk = e >> 4;
            int cc4 = (e & 15) << 2;
            float4 v = *(const float4*)(W + (size_t)(kc + kk) * ZC + c0 + cc4);
            *(float4*)&Bs[kk][cc4] = v;
        }
        __syncthreads();
        #pragma unroll
        for (int kk = 0; kk < 64; kk++) {
            float4 bv = *(float4*)&Bs[kk][tx << 2];
            float a0 = As[ty * 4 + 0][kk];
            float a1 = As[ty * 4 + 1][kk];
            float a2 = As[ty * 4 + 2][kk];
            float a3 = As[ty * 4 + 3][kk];
            acc[0][0] += a0 * bv.x; acc[0][1] += a0 * bv.y; acc[0][2] += a0 * bv.z; acc[0][3] += a0 * bv.w;
            acc[1][0] += a1 * bv.x; acc[1][1] += a1 * bv.y; acc[1][2] += a1 * bv.z; acc[1][3] += a1 * bv.w;
            acc[2][0] += a2 * bv.x; acc[2][1] += a2 * bv.y; acc[2][2] += a2 * bv.z; acc[2][3] += a2 * bv.w;
            acc[3][0] += a3 * bv.x; acc[3][1] += a3 * bv.y; acc[3][2] += a3 * bv.z; acc[3][3] += a3 * bv.w;
        }
        __syncthreads();
    }

    int col = c0 + (tx << 2);            // orig col, multiple of 4
    int g  = col >> 8;
    int jj = col & 255;
    int r  = jj >> 7;
    int lj = jj & 127;
    int pcol = r * HALF + g * 128 + lj;  // 4 consecutive cols stay consecutive
    float4 bb = *(const float4*)(bias + col);
    #pragma unroll
    for (int u = 0; u < 4; u++) {
        int row = r0 + ty * 4 + u;
        float4 o;
        o.x = acc[u][0] + bb.x; o.y = acc[u][1] + bb.y;
        o.z = acc[u][2] + bb.z; o.w = acc[u][3] + bb.w;
        *(float4*)(g_XWp + (size_t)row * ZC + pcol) = o;
    }
}

// =================================================================
// Kernel 2: recurrence. 2-CTA cluster per batch; CTA r owns z cols
// jj in [r*128,(r+1)*128) of each gate. One cluster.sync per step.
// =================================================================
__global__ void __launch_bounds__(1024, 1) __cluster_dims__(2, 1, 1)
dnc_main_kernel(const float* __restrict__ mem0,
                const float* __restrict__ W_pre,
                const float* __restrict__ b_pre,
                const float* __restrict__ W_key,
                const float* __restrict__ W_beta,
                const float* __restrict__ W_teach,
                float* __restrict__ d_out,
                int out_size) {
    extern __shared__ float sm[];
    float* memS   = sm + OFF_MEM;
    float* pS     = sm + OFF_PS;
    float* zS     = sm + OFF_Z;
    float* hA     = sm + OFF_HA;
    float* hB     = sm + OFF_HB;
    float* sS     = sm + OFF_S;
    float* cS     = sm + OFF_C;
    float* readS  = sm + OFF_READ;
    float* kS     = sm + OFF_K;
    float* teachS = sm + OFF_TEACH;
    float* preS   = sm + OFF_PRE;
    float* aS     = sm + OFF_A;
    float* wS     = sm + OFF_W;
    float* hwpS   = sm + OFF_HWP;
    float* redS   = sm + OFF_RED;
    float* scal   = sm + OFF_SCAL;

    const int b   = blockIdx.y;
    const int r   = blockIdx.x;          // cluster rank (grid.x == cluster.x == 2)
    const int tid = threadIdx.x;
    const uint32_t smbase = smem_u32(sm);
    const uint32_t peer = r ^ 1;

    // ---- init ----
    {
        const float4* m0 = (const float4*)(mem0 + (size_t)b * N_SLOT * M_DIM);
        float4* ms = (float4*)memS;
        for (int i = tid; i < N_SLOT * M_DIM / 4; i += 1024) ms[i] = m0[i];
    }
    if (tid < H_DIM) { hA[tid] = 0.f; hB[tid] = 0.f; }
    if (tid < 128)   cS[tid] = 0.f;
    if (tid < M_DIM) { readS[tid] = 0.f; sS[tid] = 0.f; }
    if (tid == 0) scal[4] = 0.f;
    __syncthreads();
    CLUSTER_SYNC();   // peers may remote-write h buffers from step 0 on

    const int cg = tid & 127;   // column group (4 cols)
    const int ks = tid >> 7;    // K split 0..7 (40 rows each)

    for (int t = 0; t < T_STEPS; t++) {
        float* hN    = (t & 1) ? hB : hA;   // h_t
        float* hPrev = (t & 1) ? hA : hB;   // h_{t-1}

        // copy h_prev into s vector (read part already in sS[0..64))
        if (tid >= 64 && tid < KROWS) sS[tid] = hPrev[tid - 64];
        __syncthreads();

        // ---------- phase 1: GEMV partials: z[lc] = sum_k s[k]*Wz[k][lc] ----------
        {
            const float4* Wp = (const float4*)(g_Wz + ((size_t)r * KROWS + ks * 40) * HALF) + cg;
            const float* sv = sS + ks * 40;
            float4 a4 = make_float4(0.f, 0.f, 0.f, 0.f);
            #pragma unroll 8
            for (int k = 0; k < 40; k++) {
                float4 w = Wp[(size_t)k * 128];
                float s = sv[k];
                a4.x += s * w.x; a4.y += s * w.y; a4.z += s * w.z; a4.w += s * w.w;
            }
            *(float4*)(pS + ks * HALF + (cg << 2)) = a4;
        }
        __syncthreads();
        if (tid < HALF) {
            float acc = g_XWp[((size_t)t * BATCH + b) * ZC + r * HALF + tid];
            #pragma unroll
            for (int q = 0; q < 8; q++) acc += pS[q * HALF + tid];
            zS[tid] = acc;
        }
        __syncthreads();

        // ---------- phase 2: LSTM update on own 128-slice; h exchange ----------
        if (tid < 128) {
            float iv = zS[tid], fv = zS[128 + tid], gv = zS[256 + tid], ov = zS[384 + tid];
            float si = 1.f / (1.f + expf(-iv));
            float sf = 1.f / (1.f + expf(-fv));
            float so = 1.f / (1.f + expf(-ov));
            float cn = sf * cS[tid] + si * tanhf(gv);
            cS[tid] = cn;
            float hv = so * tanhf(cn);
            int jj = r * 128 + tid;
            hN[jj] = hv;
            uint32_t laddr = smbase + (uint32_t)(((t & 1) ? OFF_HB : OFF_HA) + jj) * 4u;
            st_peer(laddr, peer, hv);
        }
        CLUSTER_SYNC();

        // ---------- phase 3: h @ [W_pre | W_key | W_beta | W_teach] ----------
        {
            float part_acc = 0.f;
            int col = tid >> 1;
            int half = tid & 1;
            if (tid < 514) {
                const float* Wc; int ld, c2;
                if (col < 128)      { Wc = W_pre;   ld = 128; c2 = col; }
                else if (col < 192) { Wc = W_key;   ld = 64;  c2 = col - 128; }
                else if (col < 256) { Wc = W_teach; ld = 64;  c2 = col - 192; }
                else                { Wc = W_beta;  ld = 1;   c2 = 0; }
                int h0 = half * 128;
                #pragma unroll 8
                for (int hh = 0; hh < 128; hh++)
                    part_acc += hN[h0 + hh] * Wc[(size_t)(h0 + hh) * ld + c2];
                if (half) hwpS[col] = part_acc;
            }
            __syncthreads();
            if (tid < 514 && half == 0) {
                float full = part_acc + hwpS[col];
                if (col < 128)      preS[col] = full + b_pre[col];
                else if (col < 192) kS[col - 128] = full;
                else if (col < 256) teachS[col - 192] = full;
                else {
                    float x = full;
                    scal[1] = fmaxf(x, 0.f) + log1pf(expf(-fabsf(x)));
                }
            }
        }
        __syncthreads();

        // ---------- phase 4: ||k|| and loss term ----------
        if (tid < 32) {
            float k1 = kS[tid], k2 = kS[tid + 32];
            float t1 = teachS[tid], t2 = teachS[tid + 32];
            float nk = k1 * k1 + k2 * k2;
            float d1 = k1 - t1, d2 = k2 - t2;
            float ls = d1 * d1 + d2 * d2;
            #pragma unroll
            for (int o = 16; o > 0; o >>= 1) {
                nk += __shfl_xor_sync(0xffffffffu, nk, o);
                ls += __shfl_xor_sync(0xffffffffu, ls, o);
            }
            if (tid == 0) { scal[0] = sqrtf(nk); scal[4] += ls; }
        }
        __syncthreads();

        // ---------- phase 5: cosine sim (4 threads/slot) ----------
        {
            int n = tid >> 2, tt = tid & 3;
            const float4* mr = (const float4*)(memS + n * M_DIM + tt * 16);
            const float4* kk = (const float4*)(kS + tt * 16);
            float s1 = 0.f, s2 = 0.f;
            #pragma unroll
            for (int i = 0; i < 4; i++) {
                float4 mv = mr[i]; float4 kv = kk[i];
                s1 += mv.x * kv.x + mv.y * kv.y + mv.z * kv.z + mv.w * kv.w;
                s2 += mv.x * mv.x + mv.y * mv.y + mv.z * mv.z + mv.w * mv.w;
            }
            s1 += __shfl_xor_sync(0xffffffffu, s1, 1);
            s2 += __shfl_xor_sync(0xffffffffu, s2, 1);
            s1 += __shfl_xor_sync(0xffffffffu, s1, 2);
            s2 += __shfl_xor_sync(0xffffffffu, s2, 2);
            if (tt == 0) {
                float den = fmaxf(sqrtf(s2) * scal[0], 1e-8f);
                aS[n] = scal[1] * (s1 / den);
            }
        }
        __syncthreads();

        // ---------- phase 6: softmax over 256 slots ----------
        {
            float av = (tid < N_SLOT) ? aS[tid] : -1e30f;
            float mv = av;
            #pragma unroll
            for (int o = 16; o > 0; o >>= 1)
                mv = fmaxf(mv, __shfl_xor_sync(0xffffffffu, mv, o));
            if ((tid & 31) == 0) redS[tid >> 5] = mv;
            __syncthreads();
            if (tid < 32) {
                float v = redS[tid];
                #pragma unroll
                for (int o = 16; o > 0; o >>= 1)
                    v = fmaxf(v, __shfl_xor_sync(0xffffffffu, v, o));
                if (tid == 0) scal[2] = v;
            }
            __syncthreads();
            float ev = (tid < N_SLOT) ? expf(aS[tid] - scal[2]) : 0.f;
            if (tid < N_SLOT) wS[tid] = ev;
            float sv = ev;
            #pragma unroll
            for (int o = 16; o > 0; o >>= 1)
                sv += __shfl_xor_sync(0xffffffffu, sv, o);
            if ((tid & 31) == 0) redS[tid >> 5] = sv;
            __syncthreads();
            if (tid < 32) {
                float v = redS[tid];
                #pragma unroll
                for (int o = 16; o > 0; o >>= 1)
                    v += __shfl_xor_sync(0xffffffffu, v, o);
                if (tid == 0) scal[3] = v;
            }
            __syncthreads();
            if (tid < N_SLOT) wS[tid] *= (1.f / scal[3]);
        }
        __syncthreads();

        // ---------- phase 7: mem += w (x) k; read = w @ mem_new ----------
        {
            int m = tid & 63, g = tid >> 6;
            float kv = kS[m];
            float rp = 0.f;
            #pragma unroll
            for (int s = 0; s < 16; s++) {
                int n = g * 16 + s;
                float wv = wS[n];
                float v = memS[n * M_DIM + m] + wv * kv;
                memS[n * M_DIM + m] = v;
                rp += wv * v;
            }
            pS[g * M_DIM + m] = rp;
        }
        __syncthreads();
        if (tid < M_DIM) {
            float rr2 = 0.f;
            #pragma unroll
            for (int g2 = 0; g2 < 16; g2++) rr2 += pS[g2 * M_DIM + tid];
            readS[tid] = rr2;
            sS[tid] = rr2;       // read part of next step's s vector
        }
        __syncthreads();

        // ---------- phase 8: out = pre_out + read @ Wro_eff (rank 0 only) ----------
        if (r == 0 && tid < OUT_DIM) {
            float o = preS[tid];
            #pragma unroll 8
            for (int m2 = 0; m2 < M_DIM; m2++)
                o += readS[m2] * g_Wro[m2 * OUT_DIM + tid];
            d_out[((size_t)t * BATCH + b) * OUT_DIM + tid] = o;
        }
        __syncthreads();
    }

    if (r == 0 && tid == 0) g_lossPartial[b] = scal[4];
    CLUSTER_SYNC();   // don't exit while peer may still touch our SMEM
}

// =================================================================
// Kernel 3: finalize loss
// =================================================================
__global__ void finalize_kernel(float* d_out, int out_size) {
    if (threadIdx.x == 0) {
        float s = 0.f;
        for (int b = 0; b < BATCH; b++) s += g_lossPartial[b];
        d_out[out_size - 1] = s / (float)(BATCH * M_DIM);
    }
}

// =================================================================
extern "C" void kernel_launch(void* const* d_in, const int* in_sizes, int n_in,
                              void* d_out, int out_size) {
    const float* xs      = (const float*)d_in[0];
    const float* mem0    = (const float*)d_in[1];
    const float* W_lstm  = (const float*)d_in[2];
    const float* b_lstm  = (const float*)d_in[3];
    const float* W_pre   = (const float*)d_in[4];
    const float* b_pre   = (const float*)d_in[5];
    const float* W_key   = (const float*)d_in[6];
    const float* W_beta  = (const float*)d_in[7];
    const float* W_teach = (const float*)d_in[8];
    const float* W_ro    = (const float*)d_in[9];
    float* out = (float*)d_out;

    const int smem_bytes = SM_FLOATS * (int)sizeof(float);
    cudaFuncSetAttribute(dnc_main_kernel,
                         cudaFuncAttributeMaxDynamicSharedMemorySize, smem_bytes);

    int fold_total = 2 * KROWS * HALF + M_DIM * OUT_DIM;
    fold_kernel<<<(fold_total + 255) / 256, 256>>>(W_lstm, W_ro);
    xw_kernel<<<dim3(ZC / 64, T_STEPS * BATCH / 64), 256>>>(xs, W_lstm, b_lstm);
    dnc_main_kernel<<<dim3(2, BATCH), 1024, smem_bytes>>>(mem0, W_pre, b_pre,
                                                          W_key, W_beta, W_teach,
                                                          out, out_size);
    finalize_kernel<<<1, 32>>>(out, out_size);
}

// round 12
// speedup vs baseline: 1.6718x; 1.3136x over previous
#include <cuda_runtime.h>
#include <math.h>
#include <stdint.h>

// Problem constants
#define T_STEPS 128
#define BATCH   32
#define IN_DIM  128
#define OUT_DIM 128
#define N_SLOT  256
#define M_DIM   64
#define R_HEADS 4
#define H_DIM   256
#define ZC      1024   // 4*H
#define KROWS   320    // 64 folded read rows + 256 h rows
#define CL      4      // cluster size (CTAs per batch)
#define QCOLS   256    // z columns per rank (64 per gate)

// ---------------- device scratch ----------------
__device__ float g_XWp[T_STEPS * BATCH * ZC];      // x@Wx + b, permuted cols (16 MB)
__device__ float g_Wz4[CL * KROWS * QCOLS];        // blocked z-weights per rank (1.31 MB)
__device__ float g_Wp[257 * H_DIM];                // proj weights transposed [col][256]
__device__ float g_WroT[OUT_DIM * M_DIM];          // folded W_ro transposed [out][m]
__device__ float g_lossPartial[BATCH];

// ---------------- shared memory layout (floats) ----------------
#define OFF_MEM   0                          // 16384
#define OFF_PS    (OFF_MEM + N_SLOT * M_DIM) // 4096 partials (ph1: 16x256, ph7: 16x64)
#define OFF_Z     (OFF_PS + 4096)            // 256
#define OFF_HA    (OFF_Z + QCOLS)            // 256
#define OFF_HB    (OFF_HA + H_DIM)           // 256
#define OFF_S     (OFF_HB + H_DIM)           // 320
#define OFF_C     (OFF_S + KROWS)            // 64
#define OFF_READ  (OFF_C + 64)               // 64
#define OFF_K     (OFF_READ + M_DIM)         // 64
#define OFF_TEACH (OFF_K + M_DIM)            // 64
#define OFF_PRE   (OFF_TEACH + M_DIM)        // 64 (own 64-col slice of pre)
#define OFF_A     (OFF_PRE + 64)             // 256
#define OFF_W     (OFF_A + N_SLOT)           // 256
#define OFF_RED   (OFF_W + N_SLOT)           // 32
#define OFF_SCAL  (OFF_RED + 32)             // 8
#define SM_FLOATS (OFF_SCAL + 8)
// scal: [0]=||k||, [1]=beta, [2]=smax max, [3]=smax sum, [4]=loss accum

#define CLUSTER_SYNC() do { \
    asm volatile("barrier.cluster.arrive.aligned;" ::: "memory"); \
    asm volatile("barrier.cluster.wait.aligned;" ::: "memory"); \
} while (0)

__device__ __forceinline__ uint32_t smem_u32(const void* p) {
    uint32_t a;
    asm("{ .reg .u64 t; cvta.to.shared.u64 t, %1; cvt.u32.u64 %0, t; }"
        : "=r"(a) : "l"(p));
    return a;
}
// store v into the same smem offset of every OTHER CTA in the cluster
__device__ __forceinline__ void st_peers(uint32_t laddr, uint32_t myrank, float v) {
    #pragma unroll
    for (int p = 1; p < CL; p++) {
        uint32_t raddr;
        uint32_t tgt = myrank ^ (uint32_t)p;
        asm volatile("mapa.shared::cluster.u32 %0, %1, %2;"
                     : "=r"(raddr) : "r"(laddr), "r"(tgt));
        asm volatile("st.shared::cluster.f32 [%0], %1;"
                     :: "r"(raddr), "f"(v) : "memory");
    }
}

// =================================================================
// Kernel 0: prepack weights.
//  g_Wz4[r][k][lc]: lc = g*64+j -> orig col g*256 + r*64 + j;
//                   k<64 folded read rows, k>=64 h rows.
//  g_Wp[gc][i]    : transposed projection, gc: 0-127 pre | 128-191 key |
//                   192-255 teach | 256 beta.
//  g_WroT[gc][m]  : folded read-out, transposed.
// =================================================================
__global__ void fold_kernel(const float* __restrict__ W_lstm,
                            const float* __restrict__ W_pre,
                            const float* __restrict__ W_key,
                            const float* __restrict__ W_beta,
                            const float* __restrict__ W_teach,
                            const float* __restrict__ W_ro) {
    int idx = blockIdx.x * blockDim.x + threadIdx.x;
    const int NZ = CL * KROWS * QCOLS;
    const int NP = 257 * H_DIM;
    if (idx < NZ) {
        int r  = idx / (KROWS * QCOLS);
        int k  = (idx / QCOLS) % KROWS;
        int lc = idx & (QCOLS - 1);
        int g = lc >> 6, j = lc & 63;
        int col = g * 256 + r * 64 + j;
        float s;
        if (k < 64) {
            s = 0.f;
            #pragma unroll
            for (int rr = 0; rr < R_HEADS; rr++)
                s += W_lstm[(size_t)(IN_DIM + 4 * k + rr) * ZC + col];
        } else {
            s = W_lstm[(size_t)(IN_DIM + 256 + (k - 64)) * ZC + col];
        }
        g_Wz4[idx] = s;
    } else if (idx < NZ + NP) {
        int i2 = idx - NZ;
        int gc = i2 / H_DIM, i = i2 - gc * H_DIM;
        float v;
        if (gc < 128)       v = W_pre[(size_t)i * 128 + gc];
        else if (gc < 192)  v = W_key[(size_t)i * 64 + (gc - 128)];
        else if (gc < 256)  v = W_teach[(size_t)i * 64 + (gc - 192)];
        else                v = W_beta[i];
        g_Wp[i2] = v;
    } else if (idx < NZ + NP + OUT_DIM * M_DIM) {
        int i2 = idx - NZ - NP;
        int gc = i2 / M_DIM, m = i2 - gc * M_DIM;
        float s = 0.f;
        #pragma unroll
        for (int r = 0; r < R_HEADS; r++)
            s += W_ro[(size_t)(4 * m + r) * OUT_DIM + gc];
        g_WroT[i2] = s;
    }
}

// =================================================================
// Kernel 1: XW = xs @ W_lstm[0:IN,:] + b_lstm, stored with permuted columns:
//   orig col = g*256 + r*64 + j  ->  pcol = r*256 + g*64 + j
// =================================================================
__global__ void xw_kernel(const float* __restrict__ xs,
                          const float* __restrict__ W,
                          const float* __restrict__ bias) {
    __shared__ float As[64][65];
    __shared__ float Bs[64][68];

    int tid = threadIdx.x;
    int tx = tid & 15, ty = tid >> 4;
    int r0 = blockIdx.y * 64;
    int c0 = blockIdx.x * 64;

    float acc[4][4] = {};

    for (int kc = 0; kc < IN_DIM; kc += 64) {
        for (int e = tid; e < 1024; e += 256) {
            int i = e >> 4;
            int cc4 = (e & 15) << 2;
            float4 v = *(const float4*)(xs + (size_t)(r0 + i) * IN_DIM + kc + cc4);
            As[i][cc4 + 0] = v.x; As[i][cc4 + 1] = v.y;
            As[i][cc4 + 2] = v.z; As[i][cc4 + 3] = v.w;
        }
        for (int e = tid; e < 1024; e += 256) {
            int kk = e >> 4;
            int cc4 = (e & 15) << 2;
            float4 v = *(const float4*)(W + (size_t)(kc + kk) * ZC + c0 + cc4);
            *(float4*)&Bs[kk][cc4] = v;
        }
        __syncthreads();
        #pragma unroll
        for (int kk = 0; kk < 64; kk++) {
            float4 bv = *(float4*)&Bs[kk][tx << 2];
            float a0 = As[ty * 4 + 0][kk];
            float a1 = As[ty * 4 + 1][kk];
            float a2 = As[ty * 4 + 2][kk];
            float a3 = As[ty * 4 + 3][kk];
            acc[0][0] += a0 * bv.x; acc[0][1] += a0 * bv.y; acc[0][2] += a0 * bv.z; acc[0][3] += a0 * bv.w;
            acc[1][0] += a1 * bv.x; acc[1][1] += a1 * bv.y; acc[1][2] += a1 * bv.z; acc[1][3] += a1 * bv.w;
            acc[2][0] += a2 * bv.x; acc[2][1] += a2 * bv.y; acc[2][2] += a2 * bv.z; acc[2][3] += a2 * bv.w;
            acc[3][0] += a3 * bv.x; acc[3][1] += a3 * bv.y; acc[3][2] += a3 * bv.z; acc[3][3] += a3 * bv.w;
        }
        __syncthreads();
    }

    int col = c0 + (tx << 2);            // multiple of 4; j-run stays contiguous
    int g  = col >> 8;
    int r  = (col >> 6) & 3;
    int j  = col & 63;
    int pcol = r * 256 + g * 64 + j;
    float4 bb = *(const float4*)(bias + col);
    #pragma unroll
    for (int u = 0; u < 4; u++) {
        int row = r0 + ty * 4 + u;
        float4 o;
        o.x = acc[u][0] + bb.x; o.y = acc[u][1] + bb.y;
        o.z = acc[u][2] + bb.z; o.w = acc[u][3] + bb.w;
        *(float4*)(g_XWp + (size_t)row * ZC + pcol) = o;
    }
}

// =================================================================
// Kernel 2: recurrence. 4-CTA cluster per batch. Rank r owns:
//   - z cols j in [r*64,(r+1)*64) of each gate  (ph1/ph2)
//   - proj cols [r*64, r*64+64) (ph3; beta on rank3 warp 31)
//   - out cols  [r*64, r*64+64) for r<2          (ph8)
// Tail (cos/softmax/mem/read) replicated in all ranks. 2 cluster.syncs/step.
// All warp-collective shfls execute on FULLY active warps (fix for R11 hang).
// =================================================================
__global__ void __launch_bounds__(1024, 1) __cluster_dims__(CL, 1, 1)
dnc_main_kernel(const float* __restrict__ mem0,
                const float* __restrict__ b_pre,
                float* __restrict__ d_out,
                int out_size) {
    extern __shared__ float sm[];
    float* memS   = sm + OFF_MEM;
    float* pS     = sm + OFF_PS;
    float* zS     = sm + OFF_Z;
    float* hA     = sm + OFF_HA;
    float* hB     = sm + OFF_HB;
    float* sS     = sm + OFF_S;
    float* cS     = sm + OFF_C;
    float* readS  = sm + OFF_READ;
    float* kS     = sm + OFF_K;
    float* teachS = sm + OFF_TEACH;
    float* preS   = sm + OFF_PRE;
    float* aS     = sm + OFF_A;
    float* wS     = sm + OFF_W;
    float* redS   = sm + OFF_RED;
    float* scal   = sm + OFF_SCAL;

    const int b   = blockIdx.y;
    const int r   = blockIdx.x;          // cluster rank
    const int tid = threadIdx.x;
    const uint32_t smbase = smem_u32(sm);

    // ---- init ----
    {
        const float4* m0 = (const float4*)(mem0 + (size_t)b * N_SLOT * M_DIM);
        float4* ms = (float4*)memS;
        for (int i = tid; i < N_SLOT * M_DIM / 4; i += 1024) ms[i] = m0[i];
    }
    if (tid < H_DIM) { hA[tid] = 0.f; hB[tid] = 0.f; }
    if (tid < 64)    cS[tid] = 0.f;
    if (tid < M_DIM) { readS[tid] = 0.f; sS[tid] = 0.f; }
    if (tid == 0) scal[4] = 0.f;
    __syncthreads();
    CLUSTER_SYNC();   // peers' buffers initialized before any remote write

    const int cg = tid & 63;    // float4 column group within rank slice
    const int ks = tid >> 6;    // K split 0..15 (20 rows each)

    for (int t = 0; t < T_STEPS; t++) {
        float* hN    = (t & 1) ? hB : hA;   // h_t
        float* hPrev = (t & 1) ? hA : hB;   // h_{t-1}

        // assemble s = [read | h_prev]
        if (tid < H_DIM) sS[64 + tid] = hPrev[tid];
        __syncthreads();

        // ---------- phase 1: z GEMV on own 256-col slice ----------
        {
            const float4* Wp = (const float4*)(g_Wz4 + ((size_t)r * KROWS + ks * 20) * QCOLS) + cg;
            const float* sv = sS + ks * 20;
            float4 a4 = make_float4(0.f, 0.f, 0.f, 0.f);
            #pragma unroll
            for (int k = 0; k < 20; k++) {
                float4 w = Wp[(size_t)k * 64];
                float s = sv[k];
                a4.x += s * w.x; a4.y += s * w.y; a4.z += s * w.z; a4.w += s * w.w;
            }
            *(float4*)(pS + ks * QCOLS + (cg << 2)) = a4;
        }
        __syncthreads();
        if (tid < QCOLS) {
            float acc = g_XWp[((size_t)t * BATCH + b) * ZC + r * QCOLS + tid];
            #pragma unroll
            for (int q = 0; q < 16; q++) acc += pS[q * QCOLS + tid];
            zS[tid] = acc;
        }
        __syncthreads();

        // ---------- phase 2: LSTM on own 64 h-lanes; broadcast h ----------
        if (tid < 64) {
            float iv = zS[tid], fv = zS[64 + tid], gv = zS[128 + tid], ov = zS[192 + tid];
            float si = 1.f / (1.f + expf(-iv));
            float sf = 1.f / (1.f + expf(-fv));
            float so = 1.f / (1.f + expf(-ov));
            float cn = sf * cS[tid] + si * tanhf(gv);
            cS[tid] = cn;
            float hv = so * tanhf(cn);
            int hidx = r * 64 + tid;
            hN[hidx] = hv;
            uint32_t laddr = smbase + (uint32_t)(((t & 1) ? OFF_HB : OFF_HA) + hidx) * 4u;
            st_peers(laddr, (uint32_t)r, hv);
        }
        CLUSTER_SYNC();   // syncA: full h(t) everywhere

        // ---------- phase 3: proj cols slice: h @ Wp^T (transposed layout) ----------
        // 64 cols per rank, 8 threads per col -> tid < 512 (warp-aligned!)
        if (tid < 512) {
            int cl = tid >> 3, q = tid & 7;
            int gc = r * 64 + cl;
            const float4* wp = (const float4*)(g_Wp + (size_t)gc * H_DIM + q * 32);
            const float4* hv4 = (const float4*)(hN + q * 32);
            float acc = 0.f;
            #pragma unroll
            for (int i = 0; i < 8; i++) {
                float4 w = wp[i]; float4 h4 = hv4[i];
                acc += w.x * h4.x + w.y * h4.y + w.z * h4.z + w.w * h4.w;
            }
            acc += __shfl_xor_sync(0xffffffffu, acc, 1);
            acc += __shfl_xor_sync(0xffffffffu, acc, 2);
            acc += __shfl_xor_sync(0xffffffffu, acc, 4);
            if (q == 0) {
                if (gc < 128) {
                    preS[cl] = acc + b_pre[gc];      // own slice, stays local
                } else if (gc < 192) {
                    int j = gc - 128;
                    kS[j] = acc;
                    st_peers(smbase + (uint32_t)(OFF_K + j) * 4u, (uint32_t)r, acc);
                } else {
                    teachS[gc - 192] = acc;          // local only (loss on rank3)
                }
            }
        }
        // beta: rank 3, warp 31 (fully active -> safe full-mask shfl)
        if (r == 3 && tid >= 992) {
            int l = tid - 992;                       // 0..31, 8 h-elems each
            const float4* wb = (const float4*)(g_Wp + (size_t)256 * H_DIM) + l * 2;
            const float4* h4 = (const float4*)hN + l * 2;
            float4 w0 = wb[0], w1 = wb[1];
            float4 a0 = h4[0], a1 = h4[1];
            float acc = w0.x * a0.x + w0.y * a0.y + w0.z * a0.z + w0.w * a0.w
                      + w1.x * a1.x + w1.y * a1.y + w1.z * a1.z + w1.w * a1.w;
            #pragma unroll
            for (int o = 16; o > 0; o >>= 1)
                acc += __shfl_xor_sync(0xffffffffu, acc, o);
            if (l == 0) {
                float sp = fmaxf(acc, 0.f) + log1pf(expf(-fabsf(acc)));
                scal[1] = sp;
                st_peers(smbase + (uint32_t)(OFF_SCAL + 1) * 4u, 3u, sp);
            }
        }
        CLUSTER_SYNC();   // syncB: k and beta everywhere

        // ---------- phase 4: ||k|| (all ranks); loss (rank3) ----------
        if (tid < 32) {
            float k1 = kS[tid], k2 = kS[tid + 32];
            float nk = k1 * k1 + k2 * k2;
            float ls = 0.f;
            if (r == 3) {
                float t1 = teachS[tid], t2 = teachS[tid + 32];
                float d1 = k1 - t1, d2 = k2 - t2;
                ls = d1 * d1 + d2 * d2;
            }
            #pragma unroll
            for (int o = 16; o > 0; o >>= 1) {
                nk += __shfl_xor_sync(0xffffffffu, nk, o);
                ls += __shfl_xor_sync(0xffffffffu, ls, o);
            }
            if (tid == 0) { scal[0] = sqrtf(nk); if (r == 3) scal[4] += ls; }
        }
        __syncthreads();

        // ---------- phase 5: cosine sim (4 threads/slot, replicated) ----------
        {
            int n = tid >> 2, tt = tid & 3;
            const float4* mr = (const float4*)(memS + n * M_DIM + tt * 16);
            const float4* kk = (const float4*)(kS + tt * 16);
            float s1 = 0.f, s2 = 0.f;
            #pragma unroll
            for (int i = 0; i < 4; i++) {
                float4 mv = mr[i]; float4 kv = kk[i];
                s1 += mv.x * kv.x + mv.y * kv.y + mv.z * kv.z + mv.w * kv.w;
                s2 += mv.x * mv.x + mv.y * mv.y + mv.z * mv.z + mv.w * mv.w;
            }
            s1 += __shfl_xor_sync(0xffffffffu, s1, 1);
            s2 += __shfl_xor_sync(0xffffffffu, s2, 1);
            s1 += __shfl_xor_sync(0xffffffffu, s1, 2);
            s2 += __shfl_xor_sync(0xffffffffu, s2, 2);
            if (tt == 0) {
                float den = fmaxf(sqrtf(s2) * scal[0], 1e-8f);
                aS[n] = scal[1] * (s1 / den);
            }
        }
        __syncthreads();

        // ---------- phase 6: softmax over 256 slots (replicated) ----------
        {
            float av = (tid < N_SLOT) ? aS[tid] : -1e30f;
            float mv = av;
            #pragma unroll
            for (int o = 16; o > 0; o >>= 1)
                mv = fmaxf(mv, __shfl_xor_sync(0xffffffffu, mv, o));
            if ((tid & 31) == 0) redS[tid >> 5] = mv;
            __syncthreads();
            if (tid < 32) {
                float v = redS[tid];
                #pragma unroll
                for (int o = 16; o > 0; o >>= 1)
                    v = fmaxf(v, __shfl_xor_sync(0xffffffffu, v, o));
                if (tid == 0) scal[2] = v;
            }
            __syncthreads();
            float ev = (tid < N_SLOT) ? expf(aS[tid] - scal[2]) : 0.f;
            if (tid < N_SLOT) wS[tid] = ev;
            float sv = ev;
            #pragma unroll
            for (int o = 16; o > 0; o >>= 1)
                sv += __shfl_xor_sync(0xffffffffu, sv, o);
            if ((tid & 31) == 0) redS[tid >> 5] = sv;
            __syncthreads();
            if (tid < 32) {
                float v = redS[tid];
                #pragma unroll
                for (int o = 16; o > 0; o >>= 1)
                    v += __shfl_xor_sync(0xffffffffu, v, o);
                if (tid == 0) scal[3] = v;
            }
            __syncthreads();
            if (tid < N_SLOT) wS[tid] *= (1.f / scal[3]);
        }
        __syncthreads();

        // ---------- phase 7: mem += w (x) k; read = w @ mem_new (replicated) ----------
        {
            int m = tid & 63, g = tid >> 6;
            float kv = kS[m];
            float rp = 0.f;
            #pragma unroll
            for (int s = 0; s < 16; s++) {
                int n = g * 16 + s;
                float wv = wS[n];
                float v = memS[n * M_DIM + m] + wv * kv;
                memS[n * M_DIM + m] = v;
                rp += wv * v;
            }
            pS[g * M_DIM + m] = rp;
        }
        __syncthreads();
        if (tid < M_DIM) {
            float rr2 = 0.f;
            #pragma unroll
            for (int g2 = 0; g2 < 16; g2++) rr2 += pS[g2 * M_DIM + tid];
            readS[tid] = rr2;
            sS[tid] = rr2;       // read part of next step's s vector
        }
        __syncthreads();

        // ---------- phase 8: out slice (ranks 0,1): pre + read @ WroT ----------
        if (r < 2 && tid < 256) {
            int j = tid >> 2, q = tid & 3;
            int gc = r * 64 + j;
            const float4* wp = (const float4*)(g_WroT + (size_t)gc * M_DIM + q * 16);
            const float4* rv = (const float4*)(readS + q * 16);
            float acc = 0.f;
            #pragma unroll
            for (int i = 0; i < 4; i++) {
                float4 w = wp[i]; float4 rr4 = rv[i];
                acc += w.x * rr4.x + w.y * rr4.y + w.z * rr4.z + w.w * rr4.w;
            }
            acc += __shfl_xor_sync(0xffffffffu, acc, 1);
            acc += __shfl_xor_sync(0xffffffffu, acc, 2);
            if (q == 0)
                d_out[((size_t)t * BATCH + b) * OUT_DIM + gc] = preS[j] + acc;
        }
        __syncthreads();
    }

    if (r == 3 && tid == 0) g_lossPartial[b] = scal[4];
    CLUSTER_SYNC();   // don't exit while peers may touch our SMEM
}

// =================================================================
// Kernel 3: finalize loss
// =================================================================
__global__ void finalize_kernel(float* d_out, int out_size) {
    if (threadIdx.x == 0) {
        float s = 0.f;
        for (int b = 0; b < BATCH; b++) s += g_lossPartial[b];
        d_out[out_size - 1] = s / (float)(BATCH * M_DIM);
    }
}

// =================================================================
extern "C" void kernel_launch(void* const* d_in, const int* in_sizes, int n_in,
                              void* d_out, int out_size) {
    const float* xs      = (const float*)d_in[0];
    const float* mem0    = (const float*)d_in[1];
    const float* W_lstm  = (const float*)d_in[2];
    const float* b_lstm  = (const float*)d_in[3];
    const float* W_pre   = (const float*)d_in[4];
    const float* b_pre   = (const float*)d_in[5];
    const float* W_key   = (const float*)d_in[6];
    const float* W_beta  = (const float*)d_in[7];
    const float* W_teach = (const float*)d_in[8];
    const float* W_ro    = (const float*)d_in[9];
    float* out = (float*)d_out;

    const int smem_bytes = SM_FLOATS * (int)sizeof(float);
    cudaFuncSetAttribute(dnc_main_kernel,
                         cudaFuncAttributeMaxDynamicSharedMemorySize, smem_bytes);

    int fold_total = CL * KROWS * QCOLS + 257 * H_DIM + OUT_DIM * M_DIM;
    fold_kernel<<<(fold_total + 255) / 256, 256>>>(W_lstm, W_pre, W_key,
                                                   W_beta, W_teach, W_ro);
    xw_kernel<<<dim3(ZC / 64, T_STEPS * BATCH / 64), 256>>>(xs, W_lstm, b_lstm);
    dnc_main_kernel<<<dim3(CL, BATCH), 1024, smem_bytes>>>(mem0, b_pre, out, out_size);
    finalize_kernel<<<1, 32>>>(out, out_size);
}

// round 14
// speedup vs baseline: 2.0263x; 1.2121x over previous
#include <cuda_runtime.h>
#include <cuda_fp16.h>
#include <math.h>
#include <stdint.h>

// Problem constants
#define T_STEPS 128
#define BATCH   32
#define IN_DIM  128
#define OUT_DIM 128
#define N_SLOT  256
#define M_DIM   64
#define R_HEADS 4
#define H_DIM   256
#define ZC      1024   // 4*H
#define KROWS   320    // 64 folded read rows + 256 h rows
#define CL      4      // cluster size (CTAs per batch)
#define QCOLS   256    // z columns per rank (64 per gate)

// ---------------- device scratch ----------------
__device__ float g_XWp[T_STEPS * BATCH * ZC];      // x@Wx + b, permuted cols (16 MB, fp32)
__device__ __align__(16) __half g_Wz4h[CL * KROWS * QCOLS];   // z-weights fp16 (655 KB)
__device__ __align__(16) __half g_Wph[257 * H_DIM];           // proj weights fp16, transposed
__device__ __align__(16) __half g_WroTh[OUT_DIM * M_DIM];     // folded W_ro fp16, transposed
__device__ float g_lossPartial[BATCH];

// ---------------- shared memory layout (floats) ----------------
#define OFF_MEM   0                          // 16384
#define OFF_PS    (OFF_MEM + N_SLOT * M_DIM) // 8192 partials (ph1: 32x256, ph7: 16x64)
#define OFF_Z     (OFF_PS + 8192)            // 256
#define OFF_HA    (OFF_Z + QCOLS)            // 256
#define OFF_HB    (OFF_HA + H_DIM)           // 256
#define OFF_S     (OFF_HB + H_DIM)           // 320
#define OFF_C     (OFF_S + KROWS)            // 64
#define OFF_READ  (OFF_C + 64)               // 64
#define OFF_K     (OFF_READ + M_DIM)         // 64
#define OFF_TEACH (OFF_K + M_DIM)            // 64
#define OFF_PRE   (OFF_TEACH + M_DIM)        // 64 (own 64-col slice of pre)
#define OFF_A     (OFF_PRE + 64)             // 256
#define OFF_W     (OFF_A + N_SLOT)           // 256
#define OFF_RED   (OFF_W + N_SLOT)           // 32
#define OFF_SCAL  (OFF_RED + 32)             // 8
#define SM_FLOATS (OFF_SCAL + 8)
// scal: [0]=||k||, [1]=beta, [2]=smax max, [3]=smax sum, [4]=loss accum

#define CLUSTER_SYNC() do { \
    asm volatile("barrier.cluster.arrive.aligned;" ::: "memory"); \
    asm volatile("barrier.cluster.wait.aligned;" ::: "memory"); \
} while (0)

__device__ __forceinline__ uint32_t smem_u32(const void* p) {
    uint32_t a;
    asm("{ .reg .u64 t; cvta.to.shared.u64 t, %1; cvt.u32.u64 %0, t; }"
        : "=r"(a) : "l"(p));
    return a;
}
// store v into the same smem offset of every OTHER CTA in the cluster
__device__ __forceinline__ void st_peers(uint32_t laddr, uint32_t myrank, float v) {
    #pragma unroll
    for (int p = 1; p < CL; p++) {
        uint32_t raddr;
        uint32_t tgt = myrank ^ (uint32_t)p;
        asm volatile("mapa.shared::cluster.u32 %0, %1, %2;"
                     : "=r"(raddr) : "r"(laddr), "r"(tgt));
        asm volatile("st.shared::cluster.f32 [%0], %1;"
                     :: "r"(raddr), "f"(v) : "memory");
    }
}

// =================================================================
// Kernel 0: prepack weights (fp16).
//  g_Wz4h[r][k][lc]: lc = g*64+j -> orig col g*256 + r*64 + j;
//                    k<64 folded read rows, k>=64 h rows.
//  g_Wph[gc][i]    : transposed projection, gc: 0-127 pre | 128-191 key |
//                    192-255 teach | 256 beta.
//  g_WroTh[gc][m]  : folded read-out, transposed.
// =================================================================
__global__ void fold_kernel(const float* __restrict__ W_lstm,
                            const float* __restrict__ W_pre,
                            const float* __restrict__ W_key,
                            const float* __restrict__ W_beta,
                            const float* __restrict__ W_teach,
                            const float* __restrict__ W_ro) {
    int idx = blockIdx.x * blockDim.x + threadIdx.x;
    const int NZ = CL * KROWS * QCOLS;
    const int NP = 257 * H_DIM;
    if (idx < NZ) {
        int r  = idx / (KROWS * QCOLS);
        int k  = (idx / QCOLS) % KROWS;
        int lc = idx & (QCOLS - 1);
        int g = lc >> 6, j = lc & 63;
        int col = g * 256 + r * 64 + j;
        float s;
        if (k < 64) {
            s = 0.f;
            #pragma unroll
            for (int rr = 0; rr < R_HEADS; rr++)
                s += W_lstm[(size_t)(IN_DIM + 4 * k + rr) * ZC + col];
        } else {
            s = W_lstm[(size_t)(IN_DIM + 256 + (k - 64)) * ZC + col];
        }
        g_Wz4h[idx] = __float2half(s);
    } else if (idx < NZ + NP) {
        int i2 = idx - NZ;
        int gc = i2 / H_DIM, i = i2 - gc * H_DIM;
        float v;
        if (gc < 128)       v = W_pre[(size_t)i * 128 + gc];
        else if (gc < 192)  v = W_key[(size_t)i * 64 + (gc - 128)];
        else if (gc < 256)  v = W_teach[(size_t)i * 64 + (gc - 192)];
        else                v = W_beta[i];
        g_Wph[i2] = __float2half(v);
    } else if (idx < NZ + NP + OUT_DIM * M_DIM) {
        int i2 = idx - NZ - NP;
        int gc = i2 / M_DIM, m = i2 - gc * M_DIM;
        float s = 0.f;
        #pragma unroll
        for (int r = 0; r < R_HEADS; r++)
            s += W_ro[(size_t)(4 * m + r) * OUT_DIM + gc];
        g_WroTh[i2] = __float2half(s);
    }
}

// =================================================================
// Kernel 1: XW = xs @ W_lstm[0:IN,:] + b_lstm, stored with permuted columns:
//   orig col = g*256 + r*64 + j  ->  pcol = r*256 + g*64 + j
// =================================================================
__global__ void xw_kernel(const float* __restrict__ xs,
                          const float* __restrict__ W,
                          const float* __restrict__ bias) {
    __shared__ float As[64][65];
    __shared__ float Bs[64][68];

    int tid = threadIdx.x;
    int tx = tid & 15, ty = tid >> 4;
    int r0 = blockIdx.y * 64;
    int c0 = blockIdx.x * 64;

    float acc[4][4] = {};

    for (int kc = 0; kc < IN_DIM; kc += 64) {
        for (int e = tid; e < 1024; e += 256) {
            int i = e >> 4;
            int cc4 = (e & 15) << 2;
            float4 v = *(const float4*)(xs + (size_t)(r0 + i) * IN_DIM + kc + cc4);
            As[i][cc4 + 0] = v.x; As[i][cc4 + 1] = v.y;
            As[i][cc4 + 2] = v.z; As[i][cc4 + 3] = v.w;
        }
        for (int e = tid; e < 1024; e += 256) {
            int kk = e >> 4;
            int cc4 = (e & 15) << 2;
            float4 v = *(const float4*)(W + (size_t)(kc + kk) * ZC + c0 + cc4);
            *(float4*)&Bs[kk][cc4] = v;
        }
        __syncthreads();
        #pragma unroll
        for (int kk = 0; kk < 64; kk++) {
            float4 bv = *(float4*)&Bs[kk][tx << 2];
            float a0 = As[ty * 4 + 0][kk];
            float a1 = As[ty * 4 + 1][kk];
            float a2 = As[ty * 4 + 2][kk];
            float a3 = As[ty * 4 + 3][kk];
            acc[0][0] += a0 * bv.x; acc[0][1] += a0 * bv.y; acc[0][2] += a0 * bv.z; acc[0][3] += a0 * bv.w;
            acc[1][0] += a1 * bv.x; acc[1][1] += a1 * bv.y; acc[1][2] += a1 * bv.z; acc[1][3] += a1 * bv.w;
            acc[2][0] += a2 * bv.x; acc[2][1] += a2 * bv.y; acc[2][2] += a2 * bv.z; acc[2][3] += a2 * bv.w;
            acc[3][0] += a3 * bv.x; acc[3][1] += a3 * bv.y; acc[3][2] += a3 * bv.z; acc[3][3] += a3 * bv.w;
        }
        __syncthreads();
    }

    int col = c0 + (tx << 2);            // multiple of 4; j-run stays contiguous
    int g  = col >> 8;
    int r  = (col >> 6) & 3;
    int j  = col & 63;
    int pcol = r * 256 + g * 64 + j;
    float4 bb = *(const float4*)(bias + col);
    #pragma unroll
    for (int u = 0; u < 4; u++) {
        int row = r0 + ty * 4 + u;
        float4 o;
        o.x = acc[u][0] + bb.x; o.y = acc[u][1] + bb.y;
        o.z = acc[u][2] + bb.z; o.w = acc[u][3] + bb.w;
        *(float4*)(g_XWp + (size_t)row * ZC + pcol) = o;
    }
}

// =================================================================
// Kernel 2: recurrence. 4-CTA cluster per batch. Rank r owns:
//   - z cols j in [r*64,(r+1)*64) of each gate  (ph1/ph2)
//   - proj cols [r*64, r*64+64) (ph3; beta on rank3 warp 31)
//   - out cols  [r*64, r*64+64) for r<2          (ph8)
// Weights fp16, accumulate fp32. 2 cluster.syncs/step.
// =================================================================
__global__ void __launch_bounds__(1024, 1) __cluster_dims__(CL, 1, 1)
dnc_main_kernel(const float* __restrict__ mem0,
                const float* __restrict__ b_pre,
                float* __restrict__ d_out,
                int out_size) {
    extern __shared__ float sm[];
    float* memS   = sm + OFF_MEM;
    float* pS     = sm + OFF_PS;
    float* zS     = sm + OFF_Z;
    float* hA     = sm + OFF_HA;
    float* hB     = sm + OFF_HB;
    float* sS     = sm + OFF_S;
    float* cS     = sm + OFF_C;
    float* readS  = sm + OFF_READ;
    float* kS     = sm + OFF_K;
    float* teachS = sm + OFF_TEACH;
    float* preS   = sm + OFF_PRE;
    float* aS     = sm + OFF_A;
    float* wS     = sm + OFF_W;
    float* redS   = sm + OFF_RED;
    float* scal   = sm + OFF_SCAL;

    const int b   = blockIdx.y;
    const int r   = blockIdx.x;          // cluster rank
    const int tid = threadIdx.x;
    const uint32_t smbase = smem_u32(sm);

    // ---- init ----
    {
        const float4* m0 = (const float4*)(mem0 + (size_t)b * N_SLOT * M_DIM);
        float4* ms = (float4*)memS;
        for (int i = tid; i < N_SLOT * M_DIM / 4; i += 1024) ms[i] = m0[i];
    }
    if (tid < H_DIM) { hA[tid] = 0.f; hB[tid] = 0.f; }
    if (tid < 64)    cS[tid] = 0.f;
    if (tid < M_DIM) { readS[tid] = 0.f; sS[tid] = 0.f; }
    if (tid == 0) scal[4] = 0.f;
    __syncthreads();
    CLUSTER_SYNC();   // peers' buffers initialized before any remote write

    const int cg8  = tid & 31;    // 8-col group within rank slice
    const int ks32 = tid >> 5;    // K split 0..31 (10 rows each)

    for (int t = 0; t < T_STEPS; t++) {
        float* hN    = (t & 1) ? hB : hA;   // h_t
        float* hPrev = (t & 1) ? hA : hB;   // h_{t-1}

        // assemble s = [read | h_prev]
        if (tid < H_DIM) sS[64 + tid] = hPrev[tid];
        __syncthreads();

        // ---------- phase 1: z GEMV on own 256-col slice (fp16 weights) ----------
        {
            const uint4* Wp = (const uint4*)(g_Wz4h + ((size_t)r * KROWS + ks32 * 10) * QCOLS) + cg8;
            const float* sv = sS + ks32 * 10;
            float4 a0 = make_float4(0.f, 0.f, 0.f, 0.f);
            float4 a1 = make_float4(0.f, 0.f, 0.f, 0.f);
            #pragma unroll
            for (int k = 0; k < 10; k++) {
                uint4 u = Wp[(size_t)k * 32];     // 8 halves, row stride = 32 uint4
                float s = sv[k];
                const __half2* hh = (const __half2*)&u;
                float2 f0 = __half22float2(hh[0]);
                float2 f1 = __half22float2(hh[1]);
                float2 f2 = __half22float2(hh[2]);
                float2 f3 = __half22float2(hh[3]);
                a0.x += s * f0.x; a0.y += s * f0.y; a0.z += s * f1.x; a0.w += s * f1.y;
                a1.x += s * f2.x; a1.y += s * f2.y; a1.z += s * f3.x; a1.w += s * f3.y;
            }
            float* pd = pS + ks32 * QCOLS + (cg8 << 3);
            *(float4*)pd = a0;
            *(float4*)(pd + 4) = a1;
        }
        __syncthreads();
        if (tid < QCOLS) {
            float acc = g_XWp[((size_t)t * BATCH + b) * ZC + r * QCOLS + tid];
            #pragma unroll
            for (int q = 0; q < 32; q++) acc += pS[q * QCOLS + tid];
            zS[tid] = acc;
        }
        __syncthreads();

        // ---------- phase 2: LSTM on own 64 h-lanes; broadcast h ----------
        if (tid < 64) {
            float iv = zS[tid], fv = zS[64 + tid], gv = zS[128 + tid], ov = zS[192 + tid];
            float si = 1.f / (1.f + expf(-iv));
            float sf = 1.f / (1.f + expf(-fv));
            float so = 1.f / (1.f + expf(-ov));
            float cn = sf * cS[tid] + si * tanhf(gv);
            cS[tid] = cn;
            float hv = so * tanhf(cn);
            int hidx = r * 64 + tid;
            hN[hidx] = hv;
            uint32_t laddr = smbase + (uint32_t)(((t & 1) ? OFF_HB : OFF_HA) + hidx) * 4u;
            st_peers(laddr, (uint32_t)r, hv);
        }
        CLUSTER_SYNC();   // syncA: full h(t) everywhere

        // ---------- phase 3: proj cols slice: h @ Wp^T (fp16, transposed) ----------
        // 64 cols per rank, 8 threads per col -> tid < 512 (warp-aligned)
        if (tid < 512) {
            int cl = tid >> 3, q = tid & 7;
            int gc = r * 64 + cl;
            const uint4* wp = (const uint4*)(g_Wph + (size_t)gc * H_DIM + q * 32);
            const float4* hv4 = (const float4*)(hN + q * 32);
            float acc = 0.f;
            #pragma unroll
            for (int i = 0; i < 4; i++) {
                uint4 u = wp[i];
                const __half2* hh = (const __half2*)&u;
                float2 p0 = __half22float2(hh[0]);
                float2 p1 = __half22float2(hh[1]);
                float2 p2 = __half22float2(hh[2]);
                float2 p3 = __half22float2(hh[3]);
                float4 ha = hv4[i * 2], hb = hv4[i * 2 + 1];
                acc += p0.x * ha.x + p0.y * ha.y + p1.x * ha.z + p1.y * ha.w
                     + p2.x * hb.x + p2.y * hb.y + p3.x * hb.z + p3.y * hb.w;
            }
            acc += __shfl_xor_sync(0xffffffffu, acc, 1);
            acc += __shfl_xor_sync(0xffffffffu, acc, 2);
            acc += __shfl_xor_sync(0xffffffffu, acc, 4);
            if (q == 0) {
                if (gc < 128) {
                    preS[cl] = acc + b_pre[gc];      // own slice, stays local
                } else if (gc < 192) {
                    int j = gc - 128;
                    kS[j] = acc;
                    st_peers(smbase + (uint32_t)(OFF_K + j) * 4u, (uint32_t)r, acc);
                } else {
                    teachS[gc - 192] = acc;          // local only (loss on rank3)
                }
            }
        }
        // beta: rank 3, warp 31 (fully active -> safe full-mask shfl)
        if (r == 3 && tid >= 992) {
            int l = tid - 992;                       // 0..31, 8 h-elems each
            uint4 u = ((const uint4*)(g_Wph + (size_t)256 * H_DIM))[l];
            const __half2* hh = (const __half2*)&u;
            const float4* h4 = (const float4*)hN + l * 2;
            float4 a0 = h4[0], a1 = h4[1];
            float2 p0 = __half22float2(hh[0]);
            float2 p1 = __half22float2(hh[1]);
            float2 p2 = __half22float2(hh[2]);
            float2 p3 = __half22float2(hh[3]);
            float acc = p0.x * a0.x + p0.y * a0.y + p1.x * a0.z + p1.y * a0.w
                      + p2.x * a1.x + p2.y * a1.y + p3.x * a1.z + p3.y * a1.w;
            #pragma unroll
            for (int o = 16; o > 0; o >>= 1)
                acc += __shfl_xor_sync(0xffffffffu, acc, o);
            if (l == 0) {
                float sp = fmaxf(acc, 0.f) + log1pf(expf(-fabsf(acc)));
                scal[1] = sp;
                st_peers(smbase + (uint32_t)(OFF_SCAL + 1) * 4u, 3u, sp);
            }
        }
        CLUSTER_SYNC();   // syncB: k and beta everywhere

        // ---------- phase 4: ||k|| (all ranks); loss (rank3) ----------
        if (tid < 32) {
            float k1 = kS[tid], k2 = kS[tid + 32];
            float nk = k1 * k1 + k2 * k2;
            float ls = 0.f;
            if (r == 3) {
                float t1 = teachS[tid], t2 = teachS[tid + 32];
                float d1 = k1 - t1, d2 = k2 - t2;
                ls = d1 * d1 + d2 * d2;
            }
            #pragma unroll
            for (int o = 16; o > 0; o >>= 1) {
                nk += __shfl_xor_sync(0xffffffffu, nk, o);
                ls += __shfl_xor_sync(0xffffffffu, ls, o);
            }
            if (tid == 0) { scal[0] = sqrtf(nk); if (r == 3) scal[4] += ls; }
        }
        __syncthreads();

        // ---------- phase 5: cosine sim (4 threads/slot, replicated) ----------
        {
            int n = tid >> 2, tt = tid & 3;
            const float4* mr = (const float4*)(memS + n * M_DIM + tt * 16);
            const float4* kk = (const float4*)(kS + tt * 16);
            float s1 = 0.f, s2 = 0.f;
            #pragma unroll
            for (int i = 0; i < 4; i++) {
                float4 mv = mr[i]; float4 kv = kk[i];
                s1 += mv.x * kv.x + mv.y * kv.y + mv.z * kv.z + mv.w * kv.w;
                s2 += mv.x * mv.x + mv.y * mv.y + mv.z * mv.z + mv.w * mv.w;
            }
            s1 += __shfl_xor_sync(0xffffffffu, s1, 1);
            s2 += __shfl_xor_sync(0xffffffffu, s2, 1);
            s1 += __shfl_xor_sync(0xffffffffu, s1, 2);
            s2 += __shfl_xor_sync(0xffffffffu, s2, 2);
            if (tt == 0) {
                float den = fmaxf(sqrtf(s2) * scal[0], 1e-8f);
                aS[n] = scal[1] * (s1 / den);
            }
        }
        __syncthreads();

        // ---------- phase 6: softmax over 256 slots (replicated) ----------
        {
            float av = (tid < N_SLOT) ? aS[tid] : -1e30f;
            float mv = av;
            #pragma unroll
            for (int o = 16; o > 0; o >>= 1)
                mv = fmaxf(mv, __shfl_xor_sync(0xffffffffu, mv, o));
            if ((tid & 31) == 0) redS[tid >> 5] = mv;
            __syncthreads();
            if (tid < 32) {
                float v = redS[tid];
                #pragma unroll
                for (int o = 16; o > 0; o >>= 1)
                    v = fmaxf(v, __shfl_xor_sync(0xffffffffu, v, o));
                if (tid == 0) scal[2] = v;
            }
            __syncthreads();
            float ev = (tid < N_SLOT) ? expf(aS[tid] - scal[2]) : 0.f;
            if (tid < N_SLOT) wS[tid] = ev;
            float sv = ev;
            #pragma unroll
            for (int o = 16; o > 0; o >>= 1)
                sv += __shfl_xor_sync(0xffffffffu, sv, o);
            if ((tid & 31) == 0) redS[tid >> 5] = sv;
            __syncthreads();
            if (tid < 32) {
                float v = redS[tid];
                #pragma unroll
                for (int o = 16; o > 0; o >>= 1)
                    v += __shfl_xor_sync(0xffffffffu, v, o);
                if (tid == 0) scal[3] = v;
            }
            __syncthreads();
            if (tid < N_SLOT) wS[tid] *= (1.f / scal[3]);
        }
        __syncthreads();

        // ---------- phase 7: mem += w (x) k; read = w @ mem_new (replicated) ----------
        {
            int m = tid & 63, g = tid >> 6;
            float kv = kS[m];
            float rp = 0.f;
            #pragma unroll
            for (int s = 0; s < 16; s++) {
                int n = g * 16 + s;
                float wv = wS[n];
                float v = memS[n * M_DIM + m] + wv * kv;
                memS[n * M_DIM + m] = v;
                rp += wv * v;
            }
            pS[g * M_DIM + m] = rp;
        }
        __syncthreads();
        if (tid < M_DIM) {
            float rr2 = 0.f;
            #pragma unroll
            for (int g2 = 0; g2 < 16; g2++) rr2 += pS[g2 * M_DIM + tid];
            readS[tid] = rr2;
            sS[tid] = rr2;       // read part of next step's s vector
        }
        __syncthreads();

        // ---------- phase 8: out slice (ranks 0,1): pre + read @ WroT (fp16) ----------
        if (r < 2 && tid < 256) {
            int j = tid >> 2, q = tid & 3;
            int gc = r * 64 + j;
            const uint4* wp = (const uint4*)(g_WroTh + (size_t)gc * M_DIM + q * 16);
            const float4* rv = (const float4*)(readS + q * 16);
            float acc = 0.f;
            #pragma unroll
            for (int i = 0; i < 2; i++) {
                uint4 u = wp[i];
                const __half2* hh = (const __half2*)&u;
                float2 p0 = __half22float2(hh[0]);
                float2 p1 = __half22float2(hh[1]);
                float2 p2 = __half22float2(hh[2]);
                float2 p3 = __half22float2(hh[3]);
                float4 ra = rv[i * 2], rb = rv[i * 2 + 1];
                acc += p0.x * ra.x + p0.y * ra.y + p1.x * ra.z + p1.y * ra.w
                     + p2.x * rb.x + p2.y * rb.y + p3.x * rb.z + p3.y * rb.w;
            }
            acc += __shfl_xor_sync(0xffffffffu, acc, 1);
            acc += __shfl_xor_sync(0xffffffffu, acc, 2);
            if (q == 0)
                d_out[((size_t)t * BATCH + b) * OUT_DIM + gc] = preS[j] + acc;
        }
        __syncthreads();
    }

    if (r == 3 && tid == 0) g_lossPartial[b] = scal[4];
    CLUSTER_SYNC();   // don't exit while peers may touch our SMEM
}

// =================================================================
// Kernel 3: finalize loss
// =================================================================
__global__ void finalize_kernel(float* d_out, int out_size) {
    if (threadIdx.x == 0) {
        float s = 0.f;
        for (int b = 0; b < BATCH; b++) s += g_lossPartial[b];
        d_out[out_size - 1] = s / (float)(BATCH * M_DIM);
    }
}

// =================================================================
extern "C" void kernel_launch(void* const* d_in, const int* in_sizes, int n_in,
                              void* d_out, int out_size) {
    const float* xs      = (const float*)d_in[0];
    const float* mem0    = (const float*)d_in[1];
    const float* W_lstm  = (const float*)d_in[2];
    const float* b_lstm  = (const float*)d_in[3];
    const float* W_pre   = (const float*)d_in[4];
    const float* b_pre   = (const float*)d_in[5];
    const float* W_key   = (const float*)d_in[6];
    const float* W_beta  = (const float*)d_in[7];
    const float* W_teach = (const float*)d_in[8];
    const float* W_ro    = (const float*)d_in[9];
    float* out = (float*)d_out;

    const int smem_bytes = SM_FLOATS * (int)sizeof(float);
    cudaFuncSetAttribute(dnc_main_kernel,
                         cudaFuncAttributeMaxDynamicSharedMemorySize, smem_bytes);

    int fold_total = CL * KROWS * QCOLS + 257 * H_DIM + OUT_DIM * M_DIM;
    fold_kernel<<<(fold_total + 255) / 256, 256>>>(W_lstm, W_pre, W_key,
                                                   W_beta, W_teach, W_ro);
    xw_kernel<<<dim3(ZC / 64, T_STEPS * BATCH / 64), 256>>>(xs, W_lstm, b_lstm);
    dnc_main_kernel<<<dim3(CL, BATCH), 1024, smem_bytes>>>(mem0, b_pre, out, out_size);
    finalize_kernel<<<1, 32>>>(out, out_size);
}

// round 17
// speedup vs baseline: 2.4759x; 1.2218x over previous
#include <cuda_runtime.h>
#include <cuda_fp16.h>
#include <math.h>
#include <stdint.h>

// Problem constants
#define T_STEPS 128
#define BATCH   32
#define IN_DIM  128
#define OUT_DIM 128
#define N_SLOT  256
#define M_DIM   64
#define R_HEADS 4
#define H_DIM   256
#define ZC      1024   // 4*H
#define KROWS   320    // 64 folded read rows + 256 h rows
#define CL      4      // cluster size (CTAs per batch)
#define QCOLS   256    // z columns per rank (64 per gate)

// ---------------- device scratch ----------------
__device__ float g_XWp[T_STEPS * BATCH * ZC];      // x@Wx + b, permuted cols (16 MB, fp32)
__device__ __align__(16) __half g_Wz4h[CL * KROWS * QCOLS];   // z-weights fp16 (655 KB)
__device__ __align__(16) __half g_Wph[257 * H_DIM];           // proj weights fp16, transposed
__device__ __align__(16) __half g_WroTh[OUT_DIM * M_DIM];     // folded W_ro fp16, transposed
__device__ float g_lossPartial[BATCH];

// ---------------- shared memory layout (float slots) ----------------
#define OFF_ZW    0                        // 320*256 halves = 40960 float slots (160KB)
#define OFF_PROJ  40960                    // 65*256 halves  = 8320 slots (32.5KB)
#define OFF_WRO   49280                    // 64*64 halves   = 2048 slots (8KB)
#define OFF_PS    51328                    // 2048 floats (ph1: 8x256 partials, ph7: 32x64)
#define OFF_Z     53376                    // 256
#define OFF_HA    53632                    // 256
#define OFF_HB    53888                    // 256
#define OFF_S     54144                    // 320
#define OFF_C     54464                    // 64
#define OFF_READ  54528                    // 64
#define OFF_K     54592                    // 64
#define OFF_TEACH 54656                    // 64
#define OFF_PRE   54720                    // 64
#define OFF_A     54784                    // 256
#define OFF_W     55040                    // 256
#define OFF_S1    55296                    // 256  (mem_old . k per slot)
#define OFF_NSQ   55552                    // 256  (||mem_n||^2, incremental)
#define OFF_RED   55808                    // 32
#define OFF_SCAL  55840                    // 8
#define SM_FLOATS 55848                    // 223392 bytes
// scal: [0]=||k||, [1]=beta, [2]=smax max, [3]=smax sum, [4]=loss accum

#define CLUSTER_SYNC() do { \
    asm volatile("barrier.cluster.arrive.aligned;" ::: "memory"); \
    asm volatile("barrier.cluster.wait.aligned;" ::: "memory"); \
} while (0)

__device__ __forceinline__ uint32_t smem_u32(const void* p) {
    uint32_t a;
    asm("{ .reg .u64 t; cvta.to.shared.u64 t, %1; cvt.u32.u64 %0, t; }"
        : "=r"(a) : "l"(p));
    return a;
}
// store v into the same smem offset of every OTHER CTA in the cluster
__device__ __forceinline__ void st_peers(uint32_t laddr, uint32_t myrank, float v) {
    #pragma unroll
    for (int p = 1; p < CL; p++) {
        uint32_t raddr;
        uint32_t tgt = myrank ^ (uint32_t)p;
        asm volatile("mapa.shared::cluster.u32 %0, %1, %2;"
                     : "=r"(raddr) : "r"(laddr), "r"(tgt));
        asm volatile("st.shared::cluster.f32 [%0], %1;"
                     :: "r"(raddr), "f"(v) : "memory");
    }
}

// =================================================================
// Kernel 0: prepack weights (fp16). Same layouts as R14.
// =================================================================
__global__ void fold_kernel(const float* __restrict__ W_lstm,
                            const float* __restrict__ W_pre,
                            const float* __restrict__ W_key,
                            const float* __restrict__ W_beta,
                            const float* __restrict__ W_teach,
                            const float* __restrict__ W_ro) {
    int idx = blockIdx.x * blockDim.x + threadIdx.x;
    const int NZ = CL * KROWS * QCOLS;
    const int NP = 257 * H_DIM;
    if (idx < NZ) {
        int r  = idx / (KROWS * QCOLS);
        int k  = (idx / QCOLS) % KROWS;
        int lc = idx & (QCOLS - 1);
        int g = lc >> 6, j = lc & 63;
        int col = g * 256 + r * 64 + j;
        float s;
        if (k < 64) {
            s = 0.f;
            #pragma unroll
            for (int rr = 0; rr < R_HEADS; rr++)
                s += W_lstm[(size_t)(IN_DIM + 4 * k + rr) * ZC + col];
        } else {
            s = W_lstm[(size_t)(IN_DIM + 256 + (k - 64)) * ZC + col];
        }
        g_Wz4h[idx] = __float2half(s);
    } else if (idx < NZ + NP) {
        int i2 = idx - NZ;
        int gc = i2 / H_DIM, i = i2 - gc * H_DIM;
        float v;
        if (gc < 128)       v = W_pre[(size_t)i * 128 + gc];
        else if (gc < 192)  v = W_key[(size_t)i * 64 + (gc - 128)];
        else if (gc < 256)  v = W_teach[(size_t)i * 64 + (gc - 192)];
        else                v = W_beta[i];
        g_Wph[i2] = __float2half(v);
    } else if (idx < NZ + NP + OUT_DIM * M_DIM) {
        int i2 = idx - NZ - NP;
        int gc = i2 / M_DIM, m = i2 - gc * M_DIM;
        float s = 0.f;
        #pragma unroll
        for (int r = 0; r < R_HEADS; r++)
            s += W_ro[(size_t)(4 * m + r) * OUT_DIM + gc];
        g_WroTh[i2] = __float2half(s);
    }
}

// =================================================================
// Kernel 1: XW = xs @ W_lstm[0:IN,:] + b_lstm, permuted column store.
// =================================================================
__global__ void xw_kernel(const float* __restrict__ xs,
                          const float* __restrict__ W,
                          const float* __restrict__ bias) {
    __shared__ float As[64][65];
    __shared__ float Bs[64][68];

    int tid = threadIdx.x;
    int tx = tid & 15, ty = tid >> 4;
    int r0 = blockIdx.y * 64;
    int c0 = blockIdx.x * 64;

    float acc[4][4] = {};

    for (int kc = 0; kc < IN_DIM; kc += 64) {
        for (int e = tid; e < 1024; e += 256) {
            int i = e >> 4;
            int cc4 = (e & 15) << 2;
            float4 v = *(const float4*)(xs + (size_t)(r0 + i) * IN_DIM + kc + cc4);
            As[i][cc4 + 0] = v.x; As[i][cc4 + 1] = v.y;
            As[i][cc4 + 2] = v.z; As[i][cc4 + 3] = v.w;
        }
        for (int e = tid; e < 1024; e += 256) {
            int kk = e >> 4;
            int cc4 = (e & 15) << 2;
            float4 v = *(const float4*)(W + (size_t)(kc + kk) * ZC + c0 + cc4);
            *(float4*)&Bs[kk][cc4] = v;
        }
        __syncthreads();
        #pragma unroll
        for (int kk = 0; kk < 64; kk++) {
            float4 bv = *(float4*)&Bs[kk][tx << 2];
            float a0 = As[ty * 4 + 0][kk];
            float a1 = As[ty * 4 + 1][kk];
            float a2 = As[ty * 4 + 2][kk];
            float a3 = As[ty * 4 + 3][kk];
            acc[0][0] += a0 * bv.x; acc[0][1] += a0 * bv.y; acc[0][2] += a0 * bv.z; acc[0][3] += a0 * bv.w;
            acc[1][0] += a1 * bv.x; acc[1][1] += a1 * bv.y; acc[1][2] += a1 * bv.z; acc[1][3] += a1 * bv.w;
            acc[2][0] += a2 * bv.x; acc[2][1] += a2 * bv.y; acc[2][2] += a2 * bv.z; acc[2][3] += a2 * bv.w;
            acc[3][0] += a3 * bv.x; acc[3][1] += a3 * bv.y; acc[3][2] += a3 * bv.z; acc[3][3] += a3 * bv.w;
        }
        __syncthreads();
    }

    int col = c0 + (tx << 2);
    int g  = col >> 8;
    int r  = (col >> 6) & 3;
    int j  = col & 63;
    int pcol = r * 256 + g * 64 + j;
    float4 bb = *(const float4*)(bias + col);
    #pragma unroll
    for (int u = 0; u < 4; u++) {
        int row = r0 + ty * 4 + u;
        float4 o;
        o.x = acc[u][0] + bb.x; o.y = acc[u][1] + bb.y;
        o.z = acc[u][2] + bb.z; o.w = acc[u][3] + bb.w;
        *(float4*)(g_XWp + (size_t)row * ZC + pcol) = o;
    }
}

// =================================================================
// Kernel 2: recurrence. 4-CTA cluster per batch.
// Weights resident in SMEM (loaded once); memory matrix in registers
// (warp w owns slots [w*8,w*8+8); lane l holds m=l and m=l+32);
// slot norms maintained incrementally in smem.
// =================================================================
__global__ void __launch_bounds__(1024, 1) __cluster_dims__(CL, 1, 1)
dnc_main_kernel(const float* __restrict__ mem0,
                const float* __restrict__ b_pre,
                float* __restrict__ d_out,
                int out_size) {
    extern __shared__ float sm[];
    __half* zWh   = (__half*)(sm + OFF_ZW);
    __half* projh = (__half*)(sm + OFF_PROJ);
    __half* wroh  = (__half*)(sm + OFF_WRO);
    float* pS     = sm + OFF_PS;
    float* zS     = sm + OFF_Z;
    float* hA     = sm + OFF_HA;
    float* hB     = sm + OFF_HB;
    float* sS     = sm + OFF_S;
    float* cS     = sm + OFF_C;
    float* readS  = sm + OFF_READ;
    float* kS     = sm + OFF_K;
    float* teachS = sm + OFF_TEACH;
    float* preS   = sm + OFF_PRE;
    float* aS     = sm + OFF_A;
    float* wS     = sm + OFF_W;
    float* s1S    = sm + OFF_S1;
    float* nsqS   = sm + OFF_NSQ;
    float* redS   = sm + OFF_RED;
    float* scal   = sm + OFF_SCAL;

    const int b   = blockIdx.y;
    const int r   = blockIdx.x;          // cluster rank
    const int tid = threadIdx.x;
    const int wrp = tid >> 5;            // warp 0..31 (owns slots wrp*8..+8)
    const int lan = tid & 31;
    const uint32_t smbase = smem_u32(sm);

    // ---- stage weights into SMEM (once) ----
    {
        const uint4* zsrc = (const uint4*)(g_Wz4h + (size_t)r * KROWS * QCOLS);
        uint4* zdst = (uint4*)zWh;
        for (int i = tid; i < KROWS * QCOLS / 8; i += 1024) zdst[i] = zsrc[i];
        const uint4* psrc = (const uint4*)(g_Wph + (size_t)(r * 64) * H_DIM);
        uint4* pdst = (uint4*)projh;
        for (int i = tid; i < 64 * H_DIM / 8; i += 1024) pdst[i] = psrc[i];
        const uint4* bsrc = (const uint4*)(g_Wph + (size_t)256 * H_DIM);
        if (tid < 32) pdst[64 * H_DIM / 8 + tid] = bsrc[tid];
        if (r < 2) {
            const uint4* wsrc = (const uint4*)(g_WroTh + (size_t)(r * 64) * M_DIM);
            uint4* wdst = (uint4*)wroh;
            for (int i = tid; i < 64 * M_DIM / 8; i += 1024) wdst[i] = wsrc[i];
        }
    }

    // ---- memory matrix into registers; init norms ----
    float R0[8], R1[8];
    {
        const float* m0 = mem0 + (size_t)b * N_SLOT * M_DIM;
        #pragma unroll
        for (int s = 0; s < 8; s++) {
            R0[s] = m0[(size_t)(wrp * 8 + s) * M_DIM + lan];
            R1[s] = m0[(size_t)(wrp * 8 + s) * M_DIM + lan + 32];
        }
        #pragma unroll
        for (int s = 0; s < 8; s++) {
            float p = R0[s] * R0[s] + R1[s] * R1[s];
            #pragma unroll
            for (int o = 16; o > 0; o >>= 1)
                p += __shfl_xor_sync(0xffffffffu, p, o);
            if (lan == s) nsqS[wrp * 8 + s] = p;
        }
    }
    if (tid < H_DIM) { hA[tid] = 0.f; hB[tid] = 0.f; }
    if (tid < 64)    cS[tid] = 0.f;
    if (tid < M_DIM) { readS[tid] = 0.f; sS[tid] = 0.f; }
    if (tid == 0) scal[4] = 0.f;
    __syncthreads();
    CLUSTER_SYNC();   // peers' buffers initialized before any remote write

    for (int t = 0; t < T_STEPS; t++) {
        float* hN    = (t & 1) ? hB : hA;   // h_t
        float* hPrev = (t & 1) ? hA : hB;   // h_{t-1}

        // prefetch XW slice (independent LDG, consumed after ph1)
        float xwv = 0.f;
        if (tid < QCOLS) xwv = g_XWp[((size_t)t * BATCH + b) * ZC + r * QCOLS + tid];

        // assemble s = [read | h_prev]
        if (tid < H_DIM) sS[64 + tid] = hPrev[tid];
        __syncthreads();

        // ---------- phase 1: z GEMV from SMEM weights ----------
        {
            const int grp = tid & 127;    // 2-col group
            const int ksx = tid >> 7;     // K split 0..7 (40 rows each)
            const __half* wz = zWh + (size_t)(ksx * 40) * QCOLS + grp * 2;
            const float* sv = sS + ksx * 40;
            float a0 = 0.f, a1 = 0.f;
            #pragma unroll
            for (int kk2 = 0; kk2 < 40; kk2++) {
                uint32_t u = *(const uint32_t*)(wz + (size_t)kk2 * QCOLS);
                float2 f = __half22float2(*(__half2*)&u);
                float s = sv[kk2];
                a0 += s * f.x; a1 += s * f.y;
            }
            pS[ksx * QCOLS + grp * 2]     = a0;
            pS[ksx * QCOLS + grp * 2 + 1] = a1;
        }
        __syncthreads();
        if (tid < QCOLS) {
            float acc = xwv;
            #pragma unroll
            for (int q = 0; q < 8; q++) acc += pS[q * QCOLS + tid];
            zS[tid] = acc;
        }
        __syncthreads();

        // ---------- phase 2: LSTM on own 64 h-lanes; broadcast h ----------
        if (tid < 64) {
            float iv = zS[tid], fv = zS[64 + tid], gv = zS[128 + tid], ov = zS[192 + tid];
            float si = 1.f / (1.f + expf(-iv));
            float sf = 1.f / (1.f + expf(-fv));
            float so = 1.f / (1.f + expf(-ov));
            float cn = sf * cS[tid] + si * tanhf(gv);
            cS[tid] = cn;
            float hv = so * tanhf(cn);
            int hidx = r * 64 + tid;
            hN[hidx] = hv;
            uint32_t laddr = smbase + (uint32_t)(((t & 1) ? OFF_HB : OFF_HA) + hidx) * 4u;
            st_peers(laddr, (uint32_t)r, hv);
        }
        CLUSTER_SYNC();   // syncA: full h(t) everywhere

        // ---------- phase 3: own 64 proj cols from SMEM (8 thr/col) ----------
        if (tid < 512) {
            int cl = tid >> 3, q = tid & 7;
            const uint4* wp = (const uint4*)(projh + (size_t)cl * H_DIM + q * 32);
            const float4* hv4 = (const float4*)(hN + q * 32);
            float acc = 0.f;
            #pragma unroll
            for (int i = 0; i < 4; i++) {
                uint4 u = wp[i];
                const __half2* hh = (const __half2*)&u;
                float2 p0 = __half22float2(hh[0]);
                float2 p1 = __half22float2(hh[1]);
                float2 p2 = __half22float2(hh[2]);
                float2 p3 = __half22float2(hh[3]);
                float4 ha = hv4[i * 2], hb = hv4[i * 2 + 1];
                acc += p0.x * ha.x + p0.y * ha.y + p1.x * ha.z + p1.y * ha.w
                     + p2.x * hb.x + p2.y * hb.y + p3.x * hb.z + p3.y * hb.w;
            }
            acc += __shfl_xor_sync(0xffffffffu, acc, 1);
            acc += __shfl_xor_sync(0xffffffffu, acc, 2);
            acc += __shfl_xor_sync(0xffffffffu, acc, 4);
            if (q == 0) {
                if (r < 2) {
                    preS[cl] = acc + b_pre[r * 64 + cl];
                } else if (r == 2) {
                    kS[cl] = acc;
                    st_peers(smbase + (uint32_t)(OFF_K + cl) * 4u, 2u, acc);
                } else {
                    teachS[cl] = acc;
                }
            }
        }
        // beta: rank 3, warp 31 (fully active), weights at proj col 64
        if (r == 3 && tid >= 992) {
            int l = tid - 992;
            uint4 u = ((const uint4*)(projh + (size_t)64 * H_DIM))[l];
            const __half2* hh = (const __half2*)&u;
            const float4* h4 = (const float4*)hN + l * 2;
            float4 a0 = h4[0], a1 = h4[1];
            float2 p0 = __half22float2(hh[0]);
            float2 p1 = __half22float2(hh[1]);
            float2 p2 = __half22float2(hh[2]);
            float2 p3 = __half22float2(hh[3]);
            float acc = p0.x * a0.x + p0.y * a0.y + p1.x * a0.z + p1.y * a0.w
                      + p2.x * a1.x + p2.y * a1.y + p3.x * a1.z + p3.y * a1.w;
            #pragma unroll
            for (int o = 16; o > 0; o >>= 1)
                acc += __shfl_xor_sync(0xffffffffu, acc, o);
            if (l == 0) {
                float sp = fmaxf(acc, 0.f) + log1pf(expf(-fabsf(acc)));
                scal[1] = sp;
                st_peers(smbase + (uint32_t)(OFF_SCAL + 1) * 4u, 3u, sp);
            }
        }
        CLUSTER_SYNC();   // syncB: k and beta everywhere

        // ---------- phase 4: ||k|| (all ranks); loss (rank3) ----------
        if (tid < 32) {
            float k1 = kS[tid], k2 = kS[tid + 32];
            float nk = k1 * k1 + k2 * k2;
            float ls = 0.f;
            if (r == 3) {
                float t1 = teachS[tid], t2 = teachS[tid + 32];
                float d1 = k1 - t1, d2 = k2 - t2;
                ls = d1 * d1 + d2 * d2;
            }
            #pragma unroll
            for (int o = 16; o > 0; o >>= 1) {
                nk += __shfl_xor_sync(0xffffffffu, nk, o);
                ls += __shfl_xor_sync(0xffffffffu, ls, o);
            }
            if (tid == 0) { scal[0] = sqrtf(nk); if (r == 3) scal[4] += ls; }
        }
        __syncthreads();

        // ---------- phase 5: s1 = mem_old . k from registers ----------
        {
            float kl = kS[lan], kh = kS[lan + 32];
            #pragma unroll
            for (int s = 0; s < 8; s++) {
                float p = R0[s] * kl + R1[s] * kh;
                #pragma unroll
                for (int o = 16; o > 0; o >>= 1)
                    p += __shfl_xor_sync(0xffffffffu, p, o);
                if (lan == s) s1S[wrp * 8 + s] = p;
            }
        }
        __syncthreads();
        if (tid < N_SLOT) {
            float den = fmaxf(sqrtf(fmaxf(nsqS[tid], 0.f)) * scal[0], 1e-8f);
            aS[tid] = scal[1] * (s1S[tid] / den);
        }
        __syncthreads();

        // ---------- phase 6: softmax over 256 slots ----------
        {
            float av = (tid < N_SLOT) ? aS[tid] : -1e30f;
            float mv = av;
            #pragma unroll
            for (int o = 16; o > 0; o >>= 1)
                mv = fmaxf(mv, __shfl_xor_sync(0xffffffffu, mv, o));
            if ((tid & 31) == 0) redS[tid >> 5] = mv;
            __syncthreads();
            if (tid < 32) {
                float v = redS[tid];
                #pragma unroll
                for (int o = 16; o > 0; o >>= 1)
                    v = fmaxf(v, __shfl_xor_sync(0xffffffffu, v, o));
                if (tid == 0) scal[2] = v;
            }
            __syncthreads();
            float ev = (tid < N_SLOT) ? expf(aS[tid] - scal[2]) : 0.f;
            if (tid < N_SLOT) wS[tid] = ev;
            float sv = ev;
            #pragma unroll
            for (int o = 16; o > 0; o >>= 1)
                sv += __shfl_xor_sync(0xffffffffu, sv, o);
            if ((tid & 31) == 0) redS[tid >> 5] = sv;
            __syncthreads();
            if (tid < 32) {
                float v = redS[tid];
                #pragma unroll
                for (int o = 16; o > 0; o >>= 1)
                    v += __shfl_xor_sync(0xffffffffu, v, o);
                if (tid == 0) scal[3] = v;
            }
            __syncthreads();
            if (tid < N_SLOT) wS[tid] *= (1.f / scal[3]);
        }
        __syncthreads();

        // ---------- phase 7: mem += w (x) k in regs; read partials; norm update ----------
        {
            float kl = kS[lan], kh = kS[lan + 32];
            float rpl = 0.f, rph = 0.f;
            #pragma unroll
            for (int s = 0; s < 8; s++) {
                float wv = wS[wrp * 8 + s];
                R0[s] += wv * kl;
                R1[s] += wv * kh;
                rpl += wv * R0[s];
                rph += wv * R1[s];
            }
            pS[wrp * 64 + lan]      = rpl;
            pS[wrp * 64 + lan + 32] = rph;
        }
        if (tid < N_SLOT) {
            float wv = wS[tid];
            float kk = scal[0] * scal[0];
            nsqS[tid] = nsqS[tid] + 2.f * wv * s1S[tid] + wv * wv * kk;
        }
        __syncthreads();
        if (tid < M_DIM) {
            float rr2 = 0.f;
            #pragma unroll
            for (int g2 = 0; g2 < 32; g2++) rr2 += pS[g2 * 64 + tid];
            readS[tid] = rr2;
            sS[tid] = rr2;       // read part of next step's s vector
        }
        __syncthreads();

        // ---------- phase 8: out slice (ranks 0,1) from SMEM WroT ----------
        if (r < 2 && tid < 256) {
            int j = tid >> 2, q = tid & 3;
            const uint4* wp = (const uint4*)(wroh + (size_t)j * M_DIM + q * 16);
            const float4* rv = (const float4*)(readS + q * 16);
            float acc = 0.f;
            #pragma unroll
            for (int i = 0; i < 2; i++) {
                uint4 u = wp[i];
                const __half2* hh = (const __half2*)&u;
                float2 p0 = __half22float2(hh[0]);
                float2 p1 = __half22float2(hh[1]);
                float2 p2 = __half22float2(hh[2]);
                float2 p3 = __half22float2(hh[3]);
                float4 ra = rv[i * 2], rb = rv[i * 2 + 1];
                acc += p0.x * ra.x + p0.y * ra.y + p1.x * ra.z + p1.y * ra.w
                     + p2.x * rb.x + p2.y * rb.y + p3.x * rb.z + p3.y * rb.w;
            }
            acc += __shfl_xor_sync(0xffffffffu, acc, 1);
            acc += __shfl_xor_sync(0xffffffffu, acc, 2);
            if (q == 0)
                d_out[((size_t)t * BATCH + b) * OUT_DIM + r * 64 + j] = preS[j] + acc;
        }
        __syncthreads();
    }

    if (r == 3 && tid == 0) g_lossPartial[b] = scal[4];
    CLUSTER_SYNC();   // don't exit while peers may touch our SMEM
}

// =================================================================
// Kernel 3: finalize loss
// =================================================================
__global__ void finalize_kernel(float* d_out, int out_size) {
    if (threadIdx.x == 0) {
        float s = 0.f;
        for (int b = 0; b < BATCH; b++) s += g_lossPartial[b];
        d_out[out_size - 1] = s / (float)(BATCH * M_DIM);
    }
}

// =================================================================
extern "C" void kernel_launch(void* const* d_in, const int* in_sizes, int n_in,
                              void* d_out, int out_size) {
    const float* xs      = (const float*)d_in[0];
    const float* mem0    = (const float*)d_in[1];
    const float* W_lstm  = (const float*)d_in[2];
    const float* b_lstm  = (const float*)d_in[3];
    const float* W_pre   = (const float*)d_in[4];
    const float* b_pre   = (const float*)d_in[5];
    const float* W_key   = (const float*)d_in[6];
    const float* W_beta  = (const float*)d_in[7];
    const float* W_teach = (const float*)d_in[8];
    const float* W_ro    = (const float*)d_in[9];
    float* out = (float*)d_out;

    const int smem_bytes = SM_FLOATS * (int)sizeof(float);
    cudaFuncSetAttribute(dnc_main_kernel,
                         cudaFuncAttributeMaxDynamicSharedMemorySize, smem_bytes);

    int fold_total = CL * KROWS * QCOLS + 257 * H_DIM + OUT_DIM * M_DIM;
    fold_kernel<<<(fold_total + 255) / 256, 256>>>(W_lstm, W_pre, W_key,
                                                   W_beta, W_teach, W_ro);
    xw_kernel<<<dim3(ZC / 64, T_STEPS * BATCH / 64), 256>>>(xs, W_lstm, b_lstm);
    dnc_main_kernel<<<dim3(CL, BATCH), 1024, smem_bytes>>>(mem0, b_pre, out, out_size);
    finalize_kernel<<<1, 32>>>(out, out_size);
}